// round 3
// baseline (speedup 1.0000x reference)
#include <cuda_runtime.h>
#include <math.h>

#define SEQ_LEN 16384
#define D       1024
#define CSZ     128
#define NCH     128
#define NBLK    148

// ---------------- scratch (static device globals; no runtime allocs) --------
__device__ float g_K[(size_t)SEQ_LEN * D];
__device__ float g_V[(size_t)SEQ_LEN * D];
__device__ float g_Q[(size_t)SEQ_LEN * D];
__device__ float g_M[D * D];
__device__ float g_S[D * D];
__device__ float g_err[CSZ * D];
__device__ float g_alpha[NCH];
__device__ unsigned g_cnt = 0;
__device__ unsigned g_gen = 0;

__device__ __forceinline__ float silu_f(float x) { return x / (1.0f + __expf(-x)); }

// ---------------- packed f32x2 helpers (FFMA2) -------------------------------
__device__ __forceinline__ unsigned long long splat2(float a) {
    unsigned long long r;
    asm("mov.b64 %0, {%1, %1};" : "=l"(r) : "f"(a));
    return r;
}
__device__ __forceinline__ void fma2(unsigned long long& d, unsigned long long a,
                                     unsigned long long b) {
    asm("fma.rn.f32x2 %0, %1, %2, %0;" : "+l"(d) : "l"(a), "l"(b));
}
__device__ __forceinline__ float2 unpack2(unsigned long long v) {
    float2 r;
    asm("mov.b64 {%0, %1}, %2;" : "=f"(r.x), "=f"(r.y) : "l"(v));
    return r;
}

// ---------------- software grid barrier (all NBLK blocks co-resident) -------
__device__ __forceinline__ void grid_sync() {
    __syncthreads();
    if (threadIdx.x == 0) {
        __threadfence();
        unsigned gen = atomicAdd(&g_gen, 0u);
        unsigned t = atomicAdd(&g_cnt, 1u);
        if (t == NBLK - 1) {
            g_cnt = 0;
            __threadfence();
            atomicAdd(&g_gen, 1u);
        } else {
            while (atomicAdd(&g_gen, 0u) == gen) { }
        }
        __threadfence();
    }
    __syncthreads();
}

// ---------------- projection GEMM: C = silu(A @ B^T) ------------------------
__global__ __launch_bounds__(256) void proj_kernel(
    const float* __restrict__ A, const float* __restrict__ B, float* __restrict__ C)
{
    __shared__ float As[16][132];
    __shared__ float Bs[16][132];
    const int t  = threadIdx.x;
    const int tx = t & 15, ty = t >> 4;
    const int lr = t >> 2;
    const int lk = (t & 3) * 4;
    const float* Ab = A + (size_t)blockIdx.y * 128 * D;
    const float* Bb = B + (size_t)blockIdx.x * 128 * D;

    unsigned long long acc[8][4];
    #pragma unroll
    for (int i = 0; i < 8; i++)
        #pragma unroll
        for (int j = 0; j < 4; j++) acc[i][j] = 0ull;

    for (int k0 = 0; k0 < D; k0 += 16) {
        #pragma unroll
        for (int h = 0; h < 2; h++) {
            float4 va = *(const float4*)(Ab + (size_t)(lr + h * 64) * D + k0 + lk);
            As[lk + 0][lr + h * 64] = va.x; As[lk + 1][lr + h * 64] = va.y;
            As[lk + 2][lr + h * 64] = va.z; As[lk + 3][lr + h * 64] = va.w;
            float4 vb = *(const float4*)(Bb + (size_t)(lr + h * 64) * D + k0 + lk);
            Bs[lk + 0][lr + h * 64] = vb.x; Bs[lk + 1][lr + h * 64] = vb.y;
            Bs[lk + 2][lr + h * 64] = vb.z; Bs[lk + 3][lr + h * 64] = vb.w;
        }
        __syncthreads();
        #pragma unroll
        for (int kk = 0; kk < 16; kk++) {
            float a[8];
            *(float4*)&a[0] = *(float4*)&As[kk][ty * 4];
            *(float4*)&a[4] = *(float4*)&As[kk][64 + ty * 4];
            ulonglong2 b0 = *(ulonglong2*)&Bs[kk][tx * 4];
            ulonglong2 b1 = *(ulonglong2*)&Bs[kk][64 + tx * 4];
            #pragma unroll
            for (int i = 0; i < 8; i++) {
                unsigned long long s = splat2(a[i]);
                fma2(acc[i][0], s, b0.x);
                fma2(acc[i][1], s, b0.y);
                fma2(acc[i][2], s, b1.x);
                fma2(acc[i][3], s, b1.y);
            }
        }
        __syncthreads();
    }
    const int rb = blockIdx.y * 128, cb = blockIdx.x * 128;
    #pragma unroll
    for (int i = 0; i < 8; i++) {
        int r = rb + ((i < 4) ? (ty * 4 + i) : (64 + ty * 4 + (i - 4)));
        #pragma unroll
        for (int h = 0; h < 2; h++) {
            float2 p0 = unpack2(acc[i][2 * h + 0]);
            float2 p1 = unpack2(acc[i][2 * h + 1]);
            float4 v;
            v.x = silu_f(p0.x);
            v.y = silu_f(p0.y);
            v.z = silu_f(p1.x);
            v.w = silu_f(p1.y);
            *(float4*)(C + (size_t)r * D + cb + h * 64 + tx * 4) = v;
        }
    }
}

// ---------------- row-wise l2 normalization of K and Q ----------------------
__global__ __launch_bounds__(256) void l2norm_kernel(float* __restrict__ Kp, float* __restrict__ Qp)
{
    float* P = (blockIdx.y == 0) ? Kp : Qp;
    size_t base = (size_t)blockIdx.x * D + threadIdx.x * 4;
    float4 v = *(float4*)(P + base);
    float ss = v.x * v.x + v.y * v.y + v.z * v.z + v.w * v.w;
    #pragma unroll
    for (int o = 16; o > 0; o >>= 1) ss += __shfl_xor_sync(0xffffffffu, ss, o);
    __shared__ float ws[8];
    if ((threadIdx.x & 31) == 0) ws[threadIdx.x >> 5] = ss;
    __syncthreads();
    float tot = 0.f;
    #pragma unroll
    for (int i = 0; i < 8; i++) tot += ws[i];
    float sc = 1.0f / (sqrtf(tot) + 1e-8f);
    v.x *= sc; v.y *= sc; v.z *= sc; v.w *= sc;
    *(float4*)(P + base) = v;
}

// ---------------- per-chunk forgetting gate: alpha[c] ------------------------
__global__ __launch_bounds__(256) void alpha_kernel(
    const float* __restrict__ Kp, const float* __restrict__ Wf, float* __restrict__ alpha)
{
    const int c = blockIdx.x, t = threadIdx.x;
    float4 wf = *(const float4*)(Wf + t * 4);
    const float* Kc = Kp + (size_t)c * CSZ * D;
    float s = 0.f;
    #pragma unroll 4
    for (int r = 0; r < CSZ; r++) {
        float4 kv = *(const float4*)(Kc + (size_t)r * D + t * 4);
        s += kv.x * wf.x + kv.y * wf.y + kv.z * wf.z + kv.w * wf.w;
    }
    #pragma unroll
    for (int o = 16; o > 0; o >>= 1) s += __shfl_xor_sync(0xffffffffu, s, o);
    __shared__ float ws[8];
    if ((t & 31) == 0) ws[t >> 5] = s;
    __syncthreads();
    if (t == 0) {
        float tot = 0.f;
        #pragma unroll
        for (int i = 0; i < 8; i++) tot += ws[i];
        float mean = tot * (1.0f / CSZ);
        alpha[c] = 0.1f / (1.0f + __expf(-mean));
    }
}

// ---------------- persistent sequential kernel -------------------------------
// One launch handles all 128 chunks: per chunk an update phase (grad -> S,M)
// and an outerr phase (out_c = Q@M, err_{c+1} = K@M - V), grid-synced.
__global__ __launch_bounds__(512, 1) void titan_seq(
    const float* __restrict__ Kp, const float* __restrict__ Vp, const float* __restrict__ Qp,
    float* __restrict__ M, float* __restrict__ S, float* __restrict__ err,
    const float* __restrict__ alpha, float* __restrict__ out)
{
    __shared__ __align__(16) float smem[3328];
    const int t = threadIdx.x;
    const int b = blockIdx.x;
    const int tx = t & 15, ty = t >> 4;   // ty: 0..31

    // zero-init M, S (grid-stride over float4)
    {
        float4 z = make_float4(0.f, 0.f, 0.f, 0.f);
        for (int idx = b * 512 + t; idx < D * D / 4; idx += NBLK * 512) {
            ((float4*)M)[idx] = z;
            ((float4*)S)[idx] = z;
        }
    }
    grid_sync();

    for (int c = 0; c < NCH; c++) {
        // ---------------- update phase: grad = Kc^T @ err; S,M update -------
        if (b < 128) {
            const float* Kc = Kp + (size_t)c * CSZ * D;
            const float* E  = (c == 0) ? Vp : err;
            const float gs  = ((c == 0) ? -1.0f : 1.0f) * (0.01f / CSZ);
            const int i0 = (b >> 4) * 128;
            const int j0 = (b & 15) * 64;
            float* Ks  = smem;          // [16][132]
            float* Es_ = smem + 2112;   // [16][68]

            unsigned long long acc[4][2];
            #pragma unroll
            for (int i = 0; i < 4; i++) { acc[i][0] = 0ull; acc[i][1] = 0ull; }

            for (int r0 = 0; r0 < CSZ; r0 += 16) {
                {
                    int r = t >> 5, ic = t & 31;
                    *(float4*)&Ks[r * 132 + ic * 4] =
                        *(const float4*)(Kc + (size_t)(r0 + r) * D + i0 + ic * 4);
                }
                if (t < 256) {
                    int r = t >> 4, jc = t & 15;
                    *(float4*)&Es_[r * 68 + jc * 4] =
                        *(const float4*)(E + (size_t)(r0 + r) * D + j0 + jc * 4);
                }
                __syncthreads();
                #pragma unroll
                for (int kk = 0; kk < 16; kk++) {
                    float a[4];
                    *(float4*)a = *(float4*)&Ks[kk * 132 + ty * 4];
                    ulonglong2 b2 = *(ulonglong2*)&Es_[kk * 68 + tx * 4];
                    #pragma unroll
                    for (int i = 0; i < 4; i++) {
                        unsigned long long s = splat2(a[i]);
                        fma2(acc[i][0], s, b2.x);
                        fma2(acc[i][1], s, b2.y);
                    }
                }
                __syncthreads();
            }
            const float al = alpha[c];
            const float oma = 1.0f - al;
            #pragma unroll
            for (int i = 0; i < 4; i++) {
                size_t idx = (size_t)(i0 + ty * 4 + i) * D + j0 + tx * 4;
                float2 p0 = unpack2(acc[i][0]);
                float2 p1 = unpack2(acc[i][1]);
                float4 s = *(float4*)(S + idx);
                float4 m = *(float4*)(M + idx);
                s.x = 0.9f * s.x - gs * p0.x;
                s.y = 0.9f * s.y - gs * p0.y;
                s.z = 0.9f * s.z - gs * p1.x;
                s.w = 0.9f * s.w - gs * p1.y;
                m.x = oma * m.x + s.x;
                m.y = oma * m.y + s.y;
                m.z = oma * m.z + s.z;
                m.w = oma * m.w + s.w;
                *(float4*)(S + idx) = s;
                *(float4*)(M + idx) = m;
            }
        }
        grid_sync();

        // ---------------- outerr phase: out_c = Q@M; err = K_{c+1}@M - V ----
        if (b < 128 && (c < NCH - 1 || b < 64)) {
            const bool isQ = (b < 64);
            const int rt_ = isQ ? (b >> 4) : ((b >> 4) - 4);
            const int n0 = (b & 15) * 64;
            const float* A = (isQ ? (Qp + (size_t)c * CSZ * D)
                                  : (Kp + (size_t)(c + 1) * CSZ * D)) + (size_t)rt_ * 32 * D;
            float* As = smem;           // [32][33] (k-major)
            float* Bs = smem + 1056;    // [32][68]

            unsigned long long acc0 = 0ull, acc1 = 0ull;

            for (int k0 = 0; k0 < D; k0 += 32) {
                if (t < 256) {
                    int ar = t >> 3, ak = (t & 7) * 4;
                    float4 va = *(const float4*)(A + (size_t)ar * D + k0 + ak);
                    As[(ak + 0) * 33 + ar] = va.x;
                    As[(ak + 1) * 33 + ar] = va.y;
                    As[(ak + 2) * 33 + ar] = va.z;
                    As[(ak + 3) * 33 + ar] = va.w;
                }
                {
                    int kr = t >> 4, nq = t & 15;
                    *(float4*)&Bs[kr * 68 + nq * 4] =
                        *(const float4*)(M + (size_t)(k0 + kr) * D + n0 + nq * 4);
                }
                __syncthreads();
                #pragma unroll
                for (int kk = 0; kk < 32; kk++) {
                    unsigned long long s = splat2(As[kk * 33 + ty]);
                    ulonglong2 b2 = *(ulonglong2*)&Bs[kk * 68 + tx * 4];
                    fma2(acc0, s, b2.x);
                    fma2(acc1, s, b2.y);
                }
                __syncthreads();
            }
            const int row = rt_ * 32 + ty;
            const int col = n0 + tx * 4;
            float2 p0 = unpack2(acc0);
            float2 p1 = unpack2(acc1);
            if (isQ) {
                *(float4*)(out + (size_t)(c * CSZ + row) * D + col) =
                    make_float4(p0.x, p0.y, p1.x, p1.y);
            } else {
                float4 vv = *(const float4*)(Vp + (size_t)((c + 1) * CSZ + row) * D + col);
                *(float4*)(err + (size_t)row * D + col) =
                    make_float4(p0.x - vv.x, p0.y - vv.y, p1.x - vv.z, p1.y - vv.w);
            }
        }
        grid_sync();
    }
}

// ---------------- launcher ----------------------------------------------------
extern "C" void kernel_launch(void* const* d_in, const int* in_sizes, int n_in,
                              void* d_out, int out_size)
{
    const float* x  = (const float*)d_in[0];
    const float* Wk = (const float*)d_in[1];
    const float* Wv = (const float*)d_in[2];
    const float* Wq = (const float*)d_in[3];
    const float* Wf = (const float*)d_in[4];
    float* out = (float*)d_out;

    float *Kp, *Vp, *Qp, *Mp, *Sp, *errp, *alphap;
    cudaGetSymbolAddress((void**)&Kp, g_K);
    cudaGetSymbolAddress((void**)&Vp, g_V);
    cudaGetSymbolAddress((void**)&Qp, g_Q);
    cudaGetSymbolAddress((void**)&Mp, g_M);
    cudaGetSymbolAddress((void**)&Sp, g_S);
    cudaGetSymbolAddress((void**)&errp, g_err);
    cudaGetSymbolAddress((void**)&alphap, g_alpha);

    // Parallel phase: projections (state-independent), then norms + gates.
    dim3 pg(D / 128, SEQ_LEN / 128);
    proj_kernel<<<pg, 256>>>(x, Wk, Kp);
    proj_kernel<<<pg, 256>>>(x, Wv, Vp);
    proj_kernel<<<pg, 256>>>(x, Wq, Qp);
    l2norm_kernel<<<dim3(SEQ_LEN, 2), 256>>>(Kp, Qp);
    alpha_kernel<<<NCH, 256>>>(Kp, Wf, alphap);

    // Sequential phase: ONE persistent kernel (internal grid barriers).
    titan_seq<<<NBLK, 512>>>(Kp, Vp, Qp, Mp, Sp, errp, alphap, out);
}

// round 4
// speedup vs baseline: 1.2219x; 1.2219x over previous
#include <cuda_runtime.h>
#include <math.h>

#define SEQ_LEN 16384
#define D       1024
#define CSZ     128
#define NCH     128

// ---------------- scratch (static device globals; no runtime allocs) --------
__device__ float g_K[(size_t)SEQ_LEN * D];
__device__ float g_V[(size_t)SEQ_LEN * D];
__device__ float g_Q[(size_t)SEQ_LEN * D];
__device__ float g_M[D * D];
__device__ float g_S[D * D];
__device__ float g_err[CSZ * D];
__device__ float g_alpha[NCH];

__device__ __forceinline__ float silu_f(float x) { return x / (1.0f + __expf(-x)); }

// ---------------- packed f32x2 helpers (FFMA2) -------------------------------
__device__ __forceinline__ unsigned long long splat2(float a) {
    unsigned long long r;
    asm("mov.b64 %0, {%1, %1};" : "=l"(r) : "f"(a));
    return r;
}
__device__ __forceinline__ void fma2(unsigned long long& d, unsigned long long a,
                                     unsigned long long b) {
    asm("fma.rn.f32x2 %0, %1, %2, %0;" : "+l"(d) : "l"(a), "l"(b));
}
__device__ __forceinline__ float2 unpack2(unsigned long long v) {
    float2 r;
    asm("mov.b64 {%0, %1}, %2;" : "=f"(r.x), "=f"(r.y) : "l"(v));
    return r;
}

// ---------------- zero init for M, S ----------------------------------------
__global__ __launch_bounds__(256) void zero_kernel(float* __restrict__ M, float* __restrict__ S)
{
    int idx = blockIdx.x * 256 + threadIdx.x;
    float4 z = make_float4(0.f, 0.f, 0.f, 0.f);
    ((float4*)M)[idx] = z;
    ((float4*)S)[idx] = z;
}

// ---------------- projection GEMM: C = silu(A @ B^T) ------------------------
// 128x128x16 tile, 256 threads, 8x8 micro-tile, FFMA2 inner loop.
__global__ __launch_bounds__(256) void proj_kernel(
    const float* __restrict__ A, const float* __restrict__ B, float* __restrict__ C)
{
    __shared__ float As[16][132];
    __shared__ float Bs[16][132];
    const int t  = threadIdx.x;
    const int tx = t & 15, ty = t >> 4;
    const int lr = t >> 2;
    const int lk = (t & 3) * 4;
    const float* Ab = A + (size_t)blockIdx.y * 128 * D;
    const float* Bb = B + (size_t)blockIdx.x * 128 * D;

    unsigned long long acc[8][4];
    #pragma unroll
    for (int i = 0; i < 8; i++)
        #pragma unroll
        for (int j = 0; j < 4; j++) acc[i][j] = 0ull;

    for (int k0 = 0; k0 < D; k0 += 16) {
        #pragma unroll
        for (int h = 0; h < 2; h++) {
            float4 va = *(const float4*)(Ab + (size_t)(lr + h * 64) * D + k0 + lk);
            As[lk + 0][lr + h * 64] = va.x; As[lk + 1][lr + h * 64] = va.y;
            As[lk + 2][lr + h * 64] = va.z; As[lk + 3][lr + h * 64] = va.w;
            float4 vb = *(const float4*)(Bb + (size_t)(lr + h * 64) * D + k0 + lk);
            Bs[lk + 0][lr + h * 64] = vb.x; Bs[lk + 1][lr + h * 64] = vb.y;
            Bs[lk + 2][lr + h * 64] = vb.z; Bs[lk + 3][lr + h * 64] = vb.w;
        }
        __syncthreads();
        #pragma unroll
        for (int kk = 0; kk < 16; kk++) {
            float a[8];
            *(float4*)&a[0] = *(float4*)&As[kk][ty * 4];
            *(float4*)&a[4] = *(float4*)&As[kk][64 + ty * 4];
            ulonglong2 b0 = *(ulonglong2*)&Bs[kk][tx * 4];
            ulonglong2 b1 = *(ulonglong2*)&Bs[kk][64 + tx * 4];
            #pragma unroll
            for (int i = 0; i < 8; i++) {
                unsigned long long s = splat2(a[i]);
                fma2(acc[i][0], s, b0.x);
                fma2(acc[i][1], s, b0.y);
                fma2(acc[i][2], s, b1.x);
                fma2(acc[i][3], s, b1.y);
            }
        }
        __syncthreads();
    }
    const int rb = blockIdx.y * 128, cb = blockIdx.x * 128;
    #pragma unroll
    for (int i = 0; i < 8; i++) {
        int r = rb + ((i < 4) ? (ty * 4 + i) : (64 + ty * 4 + (i - 4)));
        #pragma unroll
        for (int h = 0; h < 2; h++) {
            float2 p0 = unpack2(acc[i][2 * h + 0]);
            float2 p1 = unpack2(acc[i][2 * h + 1]);
            float4 v;
            v.x = silu_f(p0.x);
            v.y = silu_f(p0.y);
            v.z = silu_f(p1.x);
            v.w = silu_f(p1.y);
            *(float4*)(C + (size_t)r * D + cb + h * 64 + tx * 4) = v;
        }
    }
}

// ---------------- row-wise l2 normalization of K and Q ----------------------
__global__ __launch_bounds__(256) void l2norm_kernel(float* __restrict__ Kp, float* __restrict__ Qp)
{
    float* P = (blockIdx.y == 0) ? Kp : Qp;
    size_t base = (size_t)blockIdx.x * D + threadIdx.x * 4;
    float4 v = *(float4*)(P + base);
    float ss = v.x * v.x + v.y * v.y + v.z * v.z + v.w * v.w;
    #pragma unroll
    for (int o = 16; o > 0; o >>= 1) ss += __shfl_xor_sync(0xffffffffu, ss, o);
    __shared__ float ws[8];
    if ((threadIdx.x & 31) == 0) ws[threadIdx.x >> 5] = ss;
    __syncthreads();
    float tot = 0.f;
    #pragma unroll
    for (int i = 0; i < 8; i++) tot += ws[i];
    float sc = 1.0f / (sqrtf(tot) + 1e-8f);
    v.x *= sc; v.y *= sc; v.z *= sc; v.w *= sc;
    *(float4*)(P + base) = v;
}

// ---------------- per-chunk forgetting gate: alpha[c] ------------------------
__global__ __launch_bounds__(256) void alpha_kernel(
    const float* __restrict__ Kp, const float* __restrict__ Wf, float* __restrict__ alpha)
{
    const int c = blockIdx.x, t = threadIdx.x;
    float4 wf = *(const float4*)(Wf + t * 4);
    const float* Kc = Kp + (size_t)c * CSZ * D;
    float s = 0.f;
    #pragma unroll 4
    for (int r = 0; r < CSZ; r++) {
        float4 kv = *(const float4*)(Kc + (size_t)r * D + t * 4);
        s += kv.x * wf.x + kv.y * wf.y + kv.z * wf.z + kv.w * wf.w;
    }
    #pragma unroll
    for (int o = 16; o > 0; o >>= 1) s += __shfl_xor_sync(0xffffffffu, s, o);
    __shared__ float ws[8];
    if ((t & 31) == 0) ws[t >> 5] = s;
    __syncthreads();
    if (t == 0) {
        float tot = 0.f;
        #pragma unroll
        for (int i = 0; i < 8; i++) tot += ws[i];
        float mean = tot * (1.0f / CSZ);
        alpha[c] = 0.1f / (1.0f + __expf(-mean));
    }
}

// ---------------- state update: grad = Kc^T @ err; S, M update --------------
// 128 blocks (16 i-tiles x 8 j-tiles), 256 threads, tile 64x128, micro 4x8.
__global__ __launch_bounds__(256) void update_kernel(
    const float* __restrict__ Kp, const float* __restrict__ Err,
    const float* __restrict__ alpha, float* __restrict__ M, float* __restrict__ S,
    int c, float errscale)
{
    __shared__ float Ks[16][68];
    __shared__ float Es[16][132];
    const int t = threadIdx.x;
    const int tx = t & 15, ty = t >> 4;        // tx 0..15 (8 cols each), ty 0..15 (4 rows each)
    const int i0 = (blockIdx.x >> 3) * 64;
    const int j0 = (blockIdx.x & 7) * 128;
    const float* Kc = Kp + (size_t)c * CSZ * D;

    unsigned long long acc[4][4];
    #pragma unroll
    for (int i = 0; i < 4; i++)
        #pragma unroll
        for (int j = 0; j < 4; j++) acc[i][j] = 0ull;

    const int lr = t >> 4;                     // 0..15
    const int lck = (t & 15) * 4;              // Ks col (64 wide)
    const int lce = (t & 15) * 8;              // Es col (128 wide)

    for (int r0 = 0; r0 < CSZ; r0 += 16) {
        *(float4*)&Ks[lr][lck] = *(const float4*)(Kc + (size_t)(r0 + lr) * D + i0 + lck);
        *(float4*)&Es[lr][lce]     = *(const float4*)(Err + (size_t)(r0 + lr) * D + j0 + lce);
        *(float4*)&Es[lr][lce + 4] = *(const float4*)(Err + (size_t)(r0 + lr) * D + j0 + lce + 4);
        __syncthreads();
        #pragma unroll
        for (int kk = 0; kk < 16; kk++) {
            float a[4];
            *(float4*)a = *(float4*)&Ks[kk][ty * 4];
            ulonglong2 b0 = *(ulonglong2*)&Es[kk][tx * 8];
            ulonglong2 b1 = *(ulonglong2*)&Es[kk][tx * 8 + 4];
            #pragma unroll
            for (int i = 0; i < 4; i++) {
                unsigned long long s = splat2(a[i]);
                fma2(acc[i][0], s, b0.x);
                fma2(acc[i][1], s, b0.y);
                fma2(acc[i][2], s, b1.x);
                fma2(acc[i][3], s, b1.y);
            }
        }
        __syncthreads();
    }
    const float al = alpha[c];
    const float oma = 1.0f - al;
    const float gs = errscale * (0.01f / CSZ);
    #pragma unroll
    for (int i = 0; i < 4; i++) {
        size_t idx = (size_t)(i0 + ty * 4 + i) * D + j0 + tx * 8;
        #pragma unroll
        for (int h = 0; h < 2; h++) {
            float2 p0 = unpack2(acc[i][2 * h + 0]);
            float2 p1 = unpack2(acc[i][2 * h + 1]);
            float4 s = *(float4*)(S + idx + h * 4);
            float4 m = *(float4*)(M + idx + h * 4);
            s.x = 0.9f * s.x - gs * p0.x;
            s.y = 0.9f * s.y - gs * p0.y;
            s.z = 0.9f * s.z - gs * p1.x;
            s.w = 0.9f * s.w - gs * p1.y;
            m.x = oma * m.x + s.x;
            m.y = oma * m.y + s.y;
            m.z = oma * m.z + s.z;
            m.w = oma * m.w + s.w;
            *(float4*)(S + idx + h * 4) = s;
            *(float4*)(M + idx + h * 4) = m;
        }
    }
}

// ---------------- combined retrieval + next-chunk error ---------------------
// grid (16 col-tiles, 8 row-tiles), 256 threads, tile 32x64 k-tile 32, micro 2x4.
// Row-tiles 0..3: out_c = Q_c @ M. Row-tiles 4..7: err = K_{c+1} @ M - V_{c+1}.
__global__ __launch_bounds__(256) void outerr_kernel(
    const float* __restrict__ Qp, const float* __restrict__ Kp, const float* __restrict__ Vp,
    const float* __restrict__ M, float* __restrict__ out, float* __restrict__ err, int c)
{
    __shared__ float As[32][34];   // k-major: As[kk][row]
    __shared__ float Bs[32][68];
    const int t = threadIdx.x;
    const int tx = t & 15, ty = t >> 4;        // tx 0..15 (4 cols), ty 0..15 (2 rows)
    const bool isQ = (blockIdx.y < 4);
    const int rtl = isQ ? blockIdx.y : (blockIdx.y - 4);
    const float* A = (isQ ? (Qp + (size_t)c * CSZ * D)
                          : (Kp + (size_t)(c + 1) * CSZ * D)) + (size_t)rtl * 32 * D;
    const int n0 = blockIdx.x * 64;

    const int ar = t >> 3;             // 0..31 (A row / B k-row)
    const int ak = (t & 7) * 4;        // A k-offset
    const int nq = (t & 7) * 8;        // B col offset

    unsigned long long acc[2][2];
    acc[0][0] = acc[0][1] = acc[1][0] = acc[1][1] = 0ull;

    for (int k0 = 0; k0 < D; k0 += 32) {
        float4 va = *(const float4*)(A + (size_t)ar * D + k0 + ak);
        As[ak + 0][ar] = va.x; As[ak + 1][ar] = va.y;
        As[ak + 2][ar] = va.z; As[ak + 3][ar] = va.w;
        *(float4*)&Bs[ar][nq]     = *(const float4*)(M + (size_t)(k0 + ar) * D + n0 + nq);
        *(float4*)&Bs[ar][nq + 4] = *(const float4*)(M + (size_t)(k0 + ar) * D + n0 + nq + 4);
        __syncthreads();
        #pragma unroll
        for (int kk = 0; kk < 32; kk++) {
            float2 a2 = *(float2*)&As[kk][ty * 2];
            ulonglong2 b = *(ulonglong2*)&Bs[kk][tx * 4];
            unsigned long long s0 = splat2(a2.x);
            unsigned long long s1 = splat2(a2.y);
            fma2(acc[0][0], s0, b.x);
            fma2(acc[0][1], s0, b.y);
            fma2(acc[1][0], s1, b.x);
            fma2(acc[1][1], s1, b.y);
        }
        __syncthreads();
    }
    const int col = n0 + tx * 4;
    #pragma unroll
    for (int i = 0; i < 2; i++) {
        const int row = rtl * 32 + ty * 2 + i;
        float2 p0 = unpack2(acc[i][0]);
        float2 p1 = unpack2(acc[i][1]);
        if (isQ) {
            *(float4*)(out + (size_t)(c * CSZ + row) * D + col) =
                make_float4(p0.x, p0.y, p1.x, p1.y);
        } else {
            float4 vv = *(const float4*)(Vp + (size_t)((c + 1) * CSZ + row) * D + col);
            *(float4*)(err + (size_t)row * D + col) =
                make_float4(p0.x - vv.x, p0.y - vv.y, p1.x - vv.z, p1.y - vv.w);
        }
    }
}

// ---------------- launcher ----------------------------------------------------
extern "C" void kernel_launch(void* const* d_in, const int* in_sizes, int n_in,
                              void* d_out, int out_size)
{
    const float* x  = (const float*)d_in[0];
    const float* Wk = (const float*)d_in[1];
    const float* Wv = (const float*)d_in[2];
    const float* Wq = (const float*)d_in[3];
    const float* Wf = (const float*)d_in[4];
    float* out = (float*)d_out;

    float *Kp, *Vp, *Qp, *Mp, *Sp, *errp, *alphap;
    cudaGetSymbolAddress((void**)&Kp, g_K);
    cudaGetSymbolAddress((void**)&Vp, g_V);
    cudaGetSymbolAddress((void**)&Qp, g_Q);
    cudaGetSymbolAddress((void**)&Mp, g_M);
    cudaGetSymbolAddress((void**)&Sp, g_S);
    cudaGetSymbolAddress((void**)&errp, g_err);
    cudaGetSymbolAddress((void**)&alphap, g_alpha);

    // Parallel phase: projections (state-independent), then norms + gates.
    dim3 pg(D / 128, SEQ_LEN / 128);
    proj_kernel<<<pg, 256>>>(x, Wk, Kp);
    proj_kernel<<<pg, 256>>>(x, Wv, Vp);
    proj_kernel<<<pg, 256>>>(x, Wq, Qp);
    l2norm_kernel<<<dim3(SEQ_LEN, 2), 256>>>(Kp, Qp);
    alpha_kernel<<<NCH, 256>>>(Kp, Wf, alphap);
    zero_kernel<<<1024, 256>>>(Mp, Sp);

    // Sequential phase: 2 kernels per chunk.
    for (int c = 0; c < NCH; c++) {
        const float* e = (c == 0) ? Vp : errp;          // err_0 = -V_0
        float esc = (c == 0) ? -1.0f : 1.0f;
        update_kernel<<<128, 256>>>(Kp, e, alphap, Mp, Sp, c, esc);
        dim3 og(16, (c < NCH - 1) ? 8 : 4);
        outerr_kernel<<<og, 256>>>(Qp, Kp, Vp, Mp, out, errp, c);
    }
}

// round 6
// speedup vs baseline: 1.3695x; 1.1208x over previous
#include <cuda_runtime.h>
#include <cuda_bf16.h>
#include <math.h>
#include <cstdint>

#define SEQ_LEN 16384
#define D       1024
#define CSZ     128
#define NCH     128

// ---------------- scratch (static device globals; no runtime allocs) --------
__device__ float g_K[(size_t)SEQ_LEN * D];
__device__ float g_V[(size_t)SEQ_LEN * D];
__device__ float g_Q[(size_t)SEQ_LEN * D];
__device__ float g_M[D * D];
__device__ float g_S[D * D];
__device__ float g_err[CSZ * D];
__device__ float g_alpha[NCH];
__device__ __nv_bfloat16 g_xh[(size_t)SEQ_LEN * D];
__device__ __nv_bfloat16 g_xl[(size_t)SEQ_LEN * D];
__device__ __nv_bfloat16 g_Wh[3 * D * D];
__device__ __nv_bfloat16 g_Wl[3 * D * D];

__device__ __forceinline__ float silu_f(float x) { return x / (1.0f + __expf(-x)); }

// ---------------- packed f32x2 helpers (FFMA2) -------------------------------
__device__ __forceinline__ unsigned long long splat2(float a) {
    unsigned long long r;
    asm("mov.b64 %0, {%1, %1};" : "=l"(r) : "f"(a));
    return r;
}
__device__ __forceinline__ void fma2(unsigned long long& d, unsigned long long a,
                                     unsigned long long b) {
    asm("fma.rn.f32x2 %0, %1, %2, %0;" : "+l"(d) : "l"(a), "l"(b));
}
__device__ __forceinline__ float2 unpack2(unsigned long long v) {
    float2 r;
    asm("mov.b64 {%0, %1}, %2;" : "=f"(r.x), "=f"(r.y) : "l"(v));
    return r;
}

// ---------------- mma.sync helpers (baseline PTX, sm_80+) -------------------
__device__ __forceinline__ uint32_t smem_u32(const void* p) {
    uint32_t a;
    asm("{ .reg .u64 t; cvta.to.shared.u64 t, %1; cvt.u32.u64 %0, t; }" : "=r"(a) : "l"(p));
    return a;
}
__device__ __forceinline__ void ldm_x4(uint32_t* r, uint32_t addr) {
    asm volatile("ldmatrix.sync.aligned.m8n8.x4.shared.b16 {%0,%1,%2,%3}, [%4];"
                 : "=r"(r[0]), "=r"(r[1]), "=r"(r[2]), "=r"(r[3]) : "r"(addr));
}
__device__ __forceinline__ void mma_bf16(float* c, const uint32_t* a, const uint32_t* b) {
    asm volatile("mma.sync.aligned.m16n8k16.row.col.f32.bf16.bf16.f32 "
                 "{%0,%1,%2,%3}, {%4,%5,%6,%7}, {%8,%9}, {%0,%1,%2,%3};"
                 : "+f"(c[0]), "+f"(c[1]), "+f"(c[2]), "+f"(c[3])
                 : "r"(a[0]), "r"(a[1]), "r"(a[2]), "r"(a[3]), "r"(b[0]), "r"(b[1]));
}

// ---------------- fp32 -> bf16 hi/lo split -----------------------------------
__global__ __launch_bounds__(256) void convert_kernel(
    const float* __restrict__ src, __nv_bfloat16* __restrict__ hi, __nv_bfloat16* __restrict__ lo)
{
    int i = blockIdx.x * 256 + threadIdx.x;
    float4 v = ((const float4*)src)[i];
    __nv_bfloat16 h0 = __float2bfloat16(v.x);
    __nv_bfloat16 h1 = __float2bfloat16(v.y);
    __nv_bfloat16 h2 = __float2bfloat16(v.z);
    __nv_bfloat16 h3 = __float2bfloat16(v.w);
    __nv_bfloat16 l0 = __float2bfloat16(v.x - __bfloat162float(h0));
    __nv_bfloat16 l1 = __float2bfloat16(v.y - __bfloat162float(h1));
    __nv_bfloat16 l2 = __float2bfloat16(v.z - __bfloat162float(h2));
    __nv_bfloat16 l3 = __float2bfloat16(v.w - __bfloat162float(h3));
    ushort4 H, L;
    H.x = __bfloat16_as_ushort(h0); H.y = __bfloat16_as_ushort(h1);
    H.z = __bfloat16_as_ushort(h2); H.w = __bfloat16_as_ushort(h3);
    L.x = __bfloat16_as_ushort(l0); L.y = __bfloat16_as_ushort(l1);
    L.z = __bfloat16_as_ushort(l2); L.w = __bfloat16_as_ushort(l3);
    ((ushort4*)hi)[i] = H;
    ((ushort4*)lo)[i] = L;
}

// ---------------- HMMA projection GEMM: C = silu(A @ W^T) -------------------
// Block 128x128 tile, 8 warps (32m x 64n each), K staged 64/chunk in smem,
// 3-term bf16 split (ah*bh + ah*bl + al*bh), fp32 accumulators.
#define ASTR 72   // smem row stride in bf16 elems (conflict-free ldmatrix)
__global__ __launch_bounds__(256) void projmma_kernel(
    const __nv_bfloat16* __restrict__ xh, const __nv_bfloat16* __restrict__ xl,
    const __nv_bfloat16* __restrict__ Wh3, const __nv_bfloat16* __restrict__ Wl3,
    float* __restrict__ Ko, float* __restrict__ Vo, float* __restrict__ Qo)
{
    extern __shared__ __nv_bfloat16 smbf[];
    __nv_bfloat16* sAh = smbf;
    __nv_bfloat16* sAl = smbf + 128 * ASTR;
    __nv_bfloat16* sBh = smbf + 2 * 128 * ASTR;
    __nv_bfloat16* sBl = smbf + 3 * 128 * ASTR;

    const int t = threadIdx.x;
    const int w = t >> 5, lane = t & 31;
    const int m0 = blockIdx.x * 128, n0 = blockIdx.y * 128;
    const int g = blockIdx.z;
    const __nv_bfloat16* Agh = xh + (size_t)m0 * D;
    const __nv_bfloat16* Agl = xl + (size_t)m0 * D;
    const __nv_bfloat16* Bgh = Wh3 + (size_t)g * D * D + (size_t)n0 * D;
    const __nv_bfloat16* Bgl = Wl3 + (size_t)g * D * D + (size_t)n0 * D;
    float* C = (g == 0) ? Ko : ((g == 1) ? Vo : Qo);

    const int wm = (w & 3) * 32, wn = (w >> 2) * 64;

    float acc[2][8][4];
    #pragma unroll
    for (int i = 0; i < 2; i++)
        #pragma unroll
        for (int j = 0; j < 8; j++)
            #pragma unroll
            for (int q = 0; q < 4; q++) acc[i][j][q] = 0.f;

    const int lt = lane >> 3, lr8 = lane & 7;
    const int a_row = (lt & 1) * 8 + lr8;     // row within 16-m frag
    const int a_k   = (lt >> 1) * 8;          // k-half
    const int b_row = (lt >> 1) * 8 + lr8;    // n within 16-n group
    const int b_k   = (lt & 1) * 8;           // k-half

    const uint32_t uAh = smem_u32(sAh), uAl = smem_u32(sAl);
    const uint32_t uBh = smem_u32(sBh), uBl = smem_u32(sBl);

    for (int kc = 0; kc < 16; kc++) {
        #pragma unroll
        for (int i = 0; i < 4; i++) {
            int idx = t + i * 256;            // 0..1023
            int row = idx >> 3, c8 = (idx & 7) * 8;
            size_t go = (size_t)row * D + kc * 64 + c8;
            int so = row * ASTR + c8;
            *(uint4*)(sAh + so) = *(const uint4*)(Agh + go);
            *(uint4*)(sAl + so) = *(const uint4*)(Agl + go);
            *(uint4*)(sBh + so) = *(const uint4*)(Bgh + go);
            *(uint4*)(sBl + so) = *(const uint4*)(Bgl + go);
        }
        __syncthreads();
        #pragma unroll
        for (int ks = 0; ks < 4; ks++) {
            uint32_t ah[2][4], al[2][4], bh[8][2], bl[8][2];
            #pragma unroll
            for (int mf = 0; mf < 2; mf++) {
                uint32_t off = (uint32_t)(((wm + mf * 16 + a_row) * ASTR + ks * 16 + a_k) * 2);
                ldm_x4(ah[mf], uAh + off);
                ldm_x4(al[mf], uAl + off);
            }
            #pragma unroll
            for (int j = 0; j < 4; j++) {
                uint32_t off = (uint32_t)(((wn + j * 16 + b_row) * ASTR + ks * 16 + b_k) * 2);
                uint32_t r[4];
                ldm_x4(r, uBh + off);
                bh[2 * j][0] = r[0]; bh[2 * j][1] = r[1];
                bh[2 * j + 1][0] = r[2]; bh[2 * j + 1][1] = r[3];
                ldm_x4(r, uBl + off);
                bl[2 * j][0] = r[0]; bl[2 * j][1] = r[1];
                bl[2 * j + 1][0] = r[2]; bl[2 * j + 1][1] = r[3];
            }
            #pragma unroll
            for (int mf = 0; mf < 2; mf++)
                #pragma unroll
                for (int nf = 0; nf < 8; nf++) {
                    mma_bf16(acc[mf][nf], ah[mf], bh[nf]);
                    mma_bf16(acc[mf][nf], ah[mf], bl[nf]);
                    mma_bf16(acc[mf][nf], al[mf], bh[nf]);
                }
        }
        __syncthreads();
    }
    // epilogue: silu + store
    const int gq = lane >> 2, t2 = (lane & 3) * 2;
    #pragma unroll
    for (int mf = 0; mf < 2; mf++) {
        const int row = m0 + wm + mf * 16 + gq;
        #pragma unroll
        for (int nf = 0; nf < 8; nf++) {
            const int col = n0 + wn + nf * 8 + t2;
            float2 v0, v1;
            v0.x = silu_f(acc[mf][nf][0]);
            v0.y = silu_f(acc[mf][nf][1]);
            v1.x = silu_f(acc[mf][nf][2]);
            v1.y = silu_f(acc[mf][nf][3]);
            *(float2*)(C + (size_t)row * D + col) = v0;
            *(float2*)(C + (size_t)(row + 8) * D + col) = v1;
        }
    }
}

// ---------------- zero init for M, S ----------------------------------------
__global__ __launch_bounds__(256) void zero_kernel(float* __restrict__ M, float* __restrict__ S)
{
    int idx = blockIdx.x * 256 + threadIdx.x;
    float4 z = make_float4(0.f, 0.f, 0.f, 0.f);
    ((float4*)M)[idx] = z;
    ((float4*)S)[idx] = z;
}

// ---------------- row-wise l2 normalization of K and Q ----------------------
__global__ __launch_bounds__(256) void l2norm_kernel(float* __restrict__ Kp, float* __restrict__ Qp)
{
    float* P = (blockIdx.y == 0) ? Kp : Qp;
    size_t base = (size_t)blockIdx.x * D + threadIdx.x * 4;
    float4 v = *(float4*)(P + base);
    float ss = v.x * v.x + v.y * v.y + v.z * v.z + v.w * v.w;
    #pragma unroll
    for (int o = 16; o > 0; o >>= 1) ss += __shfl_xor_sync(0xffffffffu, ss, o);
    __shared__ float ws[8];
    if ((threadIdx.x & 31) == 0) ws[threadIdx.x >> 5] = ss;
    __syncthreads();
    float tot = 0.f;
    #pragma unroll
    for (int i = 0; i < 8; i++) tot += ws[i];
    float sc = 1.0f / (sqrtf(tot) + 1e-8f);
    v.x *= sc; v.y *= sc; v.z *= sc; v.w *= sc;
    *(float4*)(P + base) = v;
}

// ---------------- per-chunk forgetting gate: alpha[c] ------------------------
__global__ __launch_bounds__(256) void alpha_kernel(
    const float* __restrict__ Kp, const float* __restrict__ Wf, float* __restrict__ alpha)
{
    const int c = blockIdx.x, t = threadIdx.x;
    float4 wf = *(const float4*)(Wf + t * 4);
    const float* Kc = Kp + (size_t)c * CSZ * D;
    float s = 0.f;
    #pragma unroll 4
    for (int r = 0; r < CSZ; r++) {
        float4 kv = *(const float4*)(Kc + (size_t)r * D + t * 4);
        s += kv.x * wf.x + kv.y * wf.y + kv.z * wf.z + kv.w * wf.w;
    }
    #pragma unroll
    for (int o = 16; o > 0; o >>= 1) s += __shfl_xor_sync(0xffffffffu, s, o);
    __shared__ float ws[8];
    if ((t & 31) == 0) ws[t >> 5] = s;
    __syncthreads();
    if (t == 0) {
        float tot = 0.f;
        #pragma unroll
        for (int i = 0; i < 8; i++) tot += ws[i];
        float mean = tot * (1.0f / CSZ);
        alpha[c] = 0.1f / (1.0f + __expf(-mean));
    }
}

// ---------------- state update: grad = Kc^T @ err; S, M update --------------
__global__ __launch_bounds__(256) void update_kernel(
    const float* __restrict__ Kp, const float* __restrict__ Err,
    const float* __restrict__ alpha, float* __restrict__ M, float* __restrict__ S,
    int c, float errscale)
{
    __shared__ float Ks[16][64];
    __shared__ float Es[16][64];
    const int t = threadIdx.x;
    const int tx = t & 15, ty = t >> 4;
    const int i0 = blockIdx.y * 64, j0 = blockIdx.x * 64;
    const int lr = t >> 4, lq = t & 15;
    const float* Kc = Kp + (size_t)c * CSZ * D;

    unsigned long long acc[4][2];
    #pragma unroll
    for (int i = 0; i < 4; i++) { acc[i][0] = 0ull; acc[i][1] = 0ull; }

    for (int r0 = 0; r0 < CSZ; r0 += 16) {
        *(float4*)&Ks[lr][lq * 4] = *(const float4*)(Kc + (size_t)(r0 + lr) * D + i0 + lq * 4);
        *(float4*)&Es[lr][lq * 4] = *(const float4*)(Err + (size_t)(r0 + lr) * D + j0 + lq * 4);
        __syncthreads();
        #pragma unroll
        for (int kk = 0; kk < 16; kk++) {
            float a[4];
            *(float4*)a = *(float4*)&Ks[kk][ty * 4];
            ulonglong2 b = *(ulonglong2*)&Es[kk][tx * 4];
            #pragma unroll
            for (int i = 0; i < 4; i++) {
                unsigned long long s = splat2(a[i]);
                fma2(acc[i][0], s, b.x);
                fma2(acc[i][1], s, b.y);
            }
        }
        __syncthreads();
    }
    const float al = alpha[c];
    const float oma = 1.0f - al;
    const float gsc = errscale * (0.01f / CSZ);
    #pragma unroll
    for (int i = 0; i < 4; i++) {
        size_t idx = (size_t)(i0 + ty * 4 + i) * D + j0 + tx * 4;
        float2 g0 = unpack2(acc[i][0]);
        float2 g1 = unpack2(acc[i][1]);
        float4 s = *(float4*)(S + idx);
        float4 m = *(float4*)(M + idx);
        s.x = 0.9f * s.x - gsc * g0.x;
        s.y = 0.9f * s.y - gsc * g0.y;
        s.z = 0.9f * s.z - gsc * g1.x;
        s.w = 0.9f * s.w - gsc * g1.y;
        m.x = oma * m.x + s.x;
        m.y = oma * m.y + s.y;
        m.z = oma * m.z + s.z;
        m.w = oma * m.w + s.w;
        *(float4*)(S + idx) = s;
        *(float4*)(M + idx) = m;
    }
}

// ---------------- combined retrieval + next-chunk error ---------------------
__global__ __launch_bounds__(256) void outerr_kernel(
    const float* __restrict__ Qp, const float* __restrict__ Kp, const float* __restrict__ Vp,
    const float* __restrict__ M, float* __restrict__ out, float* __restrict__ err, int c)
{
    __shared__ float As[32][33];
    __shared__ float Bs[32][64];
    const int t = threadIdx.x;
    const int tx = t & 15, ty = t >> 4;
    const bool isQ = (blockIdx.y < 4);
    const int rtile = isQ ? blockIdx.y : (blockIdx.y - 4);
    const float* A = (isQ ? (Qp + (size_t)c * CSZ * D)
                          : (Kp + (size_t)(c + 1) * CSZ * D)) + (size_t)rtile * 32 * D;
    const int n0 = blockIdx.x * 64;
    const int ar = t >> 3;
    const int ak = (t & 7) * 4;
    const int kr = t >> 4, nq = t & 15;

    unsigned long long acc[2][2];
    acc[0][0] = acc[0][1] = acc[1][0] = acc[1][1] = 0ull;

    for (int k0 = 0; k0 < D; k0 += 32) {
        float4 va = *(const float4*)(A + (size_t)ar * D + k0 + ak);
        As[ak + 0][ar] = va.x; As[ak + 1][ar] = va.y;
        As[ak + 2][ar] = va.z; As[ak + 3][ar] = va.w;
        *(float4*)&Bs[kr][nq * 4]      = *(const float4*)(M + (size_t)(k0 + kr) * D + n0 + nq * 4);
        *(float4*)&Bs[kr + 16][nq * 4] = *(const float4*)(M + (size_t)(k0 + kr + 16) * D + n0 + nq * 4);
        __syncthreads();
        #pragma unroll
        for (int kk = 0; kk < 32; kk++) {
            float a0 = As[kk][ty * 2 + 0];
            float a1 = As[kk][ty * 2 + 1];
            ulonglong2 b = *(ulonglong2*)&Bs[kk][tx * 4];
            unsigned long long s0 = splat2(a0);
            unsigned long long s1 = splat2(a1);
            fma2(acc[0][0], s0, b.x);
            fma2(acc[0][1], s0, b.y);
            fma2(acc[1][0], s1, b.x);
            fma2(acc[1][1], s1, b.y);
        }
        __syncthreads();
    }
    const int rloc = rtile * 32 + ty * 2;
    const int col = n0 + tx * 4;
    #pragma unroll
    for (int i = 0; i < 2; i++) {
        float2 p0 = unpack2(acc[i][0]);
        float2 p1 = unpack2(acc[i][1]);
        if (isQ) {
            *(float4*)(out + (size_t)(c * CSZ + rloc + i) * D + col) =
                make_float4(p0.x, p0.y, p1.x, p1.y);
        } else {
            float4 vv = *(const float4*)(Vp + (size_t)((c + 1) * CSZ + rloc + i) * D + col);
            *(float4*)(err + (size_t)(rloc + i) * D + col) =
                make_float4(p0.x - vv.x, p0.y - vv.y, p1.x - vv.z, p1.y - vv.w);
        }
    }
}

// ---------------- launcher ----------------------------------------------------
extern "C" void kernel_launch(void* const* d_in, const int* in_sizes, int n_in,
                              void* d_out, int out_size)
{
    const float* x  = (const float*)d_in[0];
    const float* Wk = (const float*)d_in[1];
    const float* Wv = (const float*)d_in[2];
    const float* Wq = (const float*)d_in[3];
    const float* Wf = (const float*)d_in[4];
    float* out = (float*)d_out;

    float *Kp, *Vp, *Qp, *Mp, *Sp, *errp, *alphap;
    __nv_bfloat16 *xh, *xl, *Wh, *Wl;
    cudaGetSymbolAddress((void**)&Kp, g_K);
    cudaGetSymbolAddress((void**)&Vp, g_V);
    cudaGetSymbolAddress((void**)&Qp, g_Q);
    cudaGetSymbolAddress((void**)&Mp, g_M);
    cudaGetSymbolAddress((void**)&Sp, g_S);
    cudaGetSymbolAddress((void**)&errp, g_err);
    cudaGetSymbolAddress((void**)&alphap, g_alpha);
    cudaGetSymbolAddress((void**)&xh, g_xh);
    cudaGetSymbolAddress((void**)&xl, g_xl);
    cudaGetSymbolAddress((void**)&Wh, g_Wh);
    cudaGetSymbolAddress((void**)&Wl, g_Wl);

    const int proj_smem = 4 * 128 * ASTR * 2;   // 73728 bytes
    cudaFuncSetAttribute(projmma_kernel, cudaFuncAttributeMaxDynamicSharedMemorySize,
                         proj_smem);

    // Parallel phase: bf16 split, tensor-core projections, norms + gates.
    convert_kernel<<<SEQ_LEN * D / 1024, 256>>>(x, xh, xl);
    convert_kernel<<<D * D / 1024, 256>>>(Wk, Wh, Wl);
    convert_kernel<<<D * D / 1024, 256>>>(Wv, Wh + D * D, Wl + D * D);
    convert_kernel<<<D * D / 1024, 256>>>(Wq, Wh + 2 * D * D, Wl + 2 * D * D);
    projmma_kernel<<<dim3(SEQ_LEN / 128, D / 128, 3), 256, proj_smem>>>(
        xh, xl, Wh, Wl, Kp, Vp, Qp);
    l2norm_kernel<<<dim3(SEQ_LEN, 2), 256>>>(Kp, Qp);
    alpha_kernel<<<NCH, 256>>>(Kp, Wf, alphap);
    zero_kernel<<<1024, 256>>>(Mp, Sp);

    // Sequential phase: 2 kernels per chunk.
    for (int c = 0; c < NCH; c++) {
        const float* e = (c == 0) ? Vp : errp;          // err_0 = -V_0
        float esc = (c == 0) ? -1.0f : 1.0f;
        update_kernel<<<dim3(16, 16), 256>>>(Kp, e, alphap, Mp, Sp, c, esc);
        dim3 og(16, (c < NCH - 1) ? 8 : 4);
        outerr_kernel<<<og, 256>>>(Qp, Kp, Vp, Mp, out, errp, c);
    }
}

// round 7
// speedup vs baseline: 1.4027x; 1.0242x over previous
#include <cuda_runtime.h>
#include <cuda_bf16.h>
#include <math.h>
#include <cstdint>

#define SEQ_LEN 16384
#define D       1024
#define CSZ     128
#define NCH     128

// ---------------- scratch (static device globals; no runtime allocs) --------
__device__ float g_K[(size_t)SEQ_LEN * D];
__device__ float g_V[(size_t)SEQ_LEN * D];
__device__ float g_Q[(size_t)SEQ_LEN * D];
__device__ float g_M[D * D];
__device__ float g_S[D * D];
__device__ float g_alpha[NCH];
__device__ __nv_bfloat16 g_xh[(size_t)SEQ_LEN * D];
__device__ __nv_bfloat16 g_xl[(size_t)SEQ_LEN * D];
__device__ __nv_bfloat16 g_Wh[3 * D * D];
__device__ __nv_bfloat16 g_Wl[3 * D * D];
__device__ __nv_bfloat16 g_Kh[(size_t)SEQ_LEN * D];
__device__ __nv_bfloat16 g_Kl[(size_t)SEQ_LEN * D];
__device__ __nv_bfloat16 g_Qh[(size_t)SEQ_LEN * D];
__device__ __nv_bfloat16 g_Ql[(size_t)SEQ_LEN * D];
__device__ __nv_bfloat16 g_Mh[D * D];
__device__ __nv_bfloat16 g_Ml[D * D];
__device__ __nv_bfloat16 g_errh[CSZ * D];
__device__ __nv_bfloat16 g_errl[CSZ * D];
__device__ __nv_bfloat16 g_e0h[CSZ * D];
__device__ __nv_bfloat16 g_e0l[CSZ * D];

__device__ __forceinline__ float silu_f(float x) { return x / (1.0f + __expf(-x)); }

// ---------------- mma.sync helpers (baseline PTX, sm_80+) -------------------
__device__ __forceinline__ uint32_t smem_u32(const void* p) {
    uint32_t a;
    asm("{ .reg .u64 t; cvta.to.shared.u64 t, %1; cvt.u32.u64 %0, t; }" : "=r"(a) : "l"(p));
    return a;
}
__device__ __forceinline__ void ldm_x4(uint32_t* r, uint32_t addr) {
    asm volatile("ldmatrix.sync.aligned.m8n8.x4.shared.b16 {%0,%1,%2,%3}, [%4];"
                 : "=r"(r[0]), "=r"(r[1]), "=r"(r[2]), "=r"(r[3]) : "r"(addr));
}
__device__ __forceinline__ void ldm_x4_t(uint32_t* r, uint32_t addr) {
    asm volatile("ldmatrix.sync.aligned.m8n8.x4.trans.shared.b16 {%0,%1,%2,%3}, [%4];"
                 : "=r"(r[0]), "=r"(r[1]), "=r"(r[2]), "=r"(r[3]) : "r"(addr));
}
__device__ __forceinline__ void mma_bf16(float* c, const uint32_t* a, const uint32_t* b) {
    asm volatile("mma.sync.aligned.m16n8k16.row.col.f32.bf16.bf16.f32 "
                 "{%0,%1,%2,%3}, {%4,%5,%6,%7}, {%8,%9}, {%0,%1,%2,%3};"
                 : "+f"(c[0]), "+f"(c[1]), "+f"(c[2]), "+f"(c[3])
                 : "r"(a[0]), "r"(a[1]), "r"(a[2]), "r"(a[3]), "r"(b[0]), "r"(b[1]));
}

// ---------------- fp32 -> bf16 hi/lo split -----------------------------------
__global__ __launch_bounds__(256) void convert_kernel(
    const float* __restrict__ src, __nv_bfloat16* __restrict__ hi, __nv_bfloat16* __restrict__ lo)
{
    int i = blockIdx.x * 256 + threadIdx.x;
    float4 v = ((const float4*)src)[i];
    __nv_bfloat16 h0 = __float2bfloat16(v.x);
    __nv_bfloat16 h1 = __float2bfloat16(v.y);
    __nv_bfloat16 h2 = __float2bfloat16(v.z);
    __nv_bfloat16 h3 = __float2bfloat16(v.w);
    __nv_bfloat16 l0 = __float2bfloat16(v.x - __bfloat162float(h0));
    __nv_bfloat16 l1 = __float2bfloat16(v.y - __bfloat162float(h1));
    __nv_bfloat16 l2 = __float2bfloat16(v.z - __bfloat162float(h2));
    __nv_bfloat16 l3 = __float2bfloat16(v.w - __bfloat162float(h3));
    ushort4 H, L;
    H.x = __bfloat16_as_ushort(h0); H.y = __bfloat16_as_ushort(h1);
    H.z = __bfloat16_as_ushort(h2); H.w = __bfloat16_as_ushort(h3);
    L.x = __bfloat16_as_ushort(l0); L.y = __bfloat16_as_ushort(l1);
    L.z = __bfloat16_as_ushort(l2); L.w = __bfloat16_as_ushort(l3);
    ((ushort4*)hi)[i] = H;
    ((ushort4*)lo)[i] = L;
}

// ---------------- HMMA projection GEMM: C = silu(A @ W^T) -------------------
#define ASTR 72
__global__ __launch_bounds__(256) void projmma_kernel(
    const __nv_bfloat16* __restrict__ xh, const __nv_bfloat16* __restrict__ xl,
    const __nv_bfloat16* __restrict__ Wh3, const __nv_bfloat16* __restrict__ Wl3,
    float* __restrict__ Ko, float* __restrict__ Vo, float* __restrict__ Qo)
{
    extern __shared__ __nv_bfloat16 smbf[];
    __nv_bfloat16* sAh = smbf;
    __nv_bfloat16* sAl = smbf + 128 * ASTR;
    __nv_bfloat16* sBh = smbf + 2 * 128 * ASTR;
    __nv_bfloat16* sBl = smbf + 3 * 128 * ASTR;

    const int t = threadIdx.x;
    const int w = t >> 5, lane = t & 31;
    const int m0 = blockIdx.x * 128, n0 = blockIdx.y * 128;
    const int g = blockIdx.z;
    const __nv_bfloat16* Agh = xh + (size_t)m0 * D;
    const __nv_bfloat16* Agl = xl + (size_t)m0 * D;
    const __nv_bfloat16* Bgh = Wh3 + (size_t)g * D * D + (size_t)n0 * D;
    const __nv_bfloat16* Bgl = Wl3 + (size_t)g * D * D + (size_t)n0 * D;
    float* C = (g == 0) ? Ko : ((g == 1) ? Vo : Qo);

    const int wm = (w & 3) * 32, wn = (w >> 2) * 64;

    float acc[2][8][4];
    #pragma unroll
    for (int i = 0; i < 2; i++)
        #pragma unroll
        for (int j = 0; j < 8; j++)
            #pragma unroll
            for (int q = 0; q < 4; q++) acc[i][j][q] = 0.f;

    const int lt = lane >> 3, lr8 = lane & 7;
    const int a_row = (lt & 1) * 8 + lr8;
    const int a_k   = (lt >> 1) * 8;
    const int b_row = (lt >> 1) * 8 + lr8;
    const int b_k   = (lt & 1) * 8;

    const uint32_t uAh = smem_u32(sAh), uAl = smem_u32(sAl);
    const uint32_t uBh = smem_u32(sBh), uBl = smem_u32(sBl);

    for (int kc = 0; kc < 16; kc++) {
        #pragma unroll
        for (int i = 0; i < 4; i++) {
            int idx = t + i * 256;
            int row = idx >> 3, c8 = (idx & 7) * 8;
            size_t go = (size_t)row * D + kc * 64 + c8;
            int so = row * ASTR + c8;
            *(uint4*)(sAh + so) = *(const uint4*)(Agh + go);
            *(uint4*)(sAl + so) = *(const uint4*)(Agl + go);
            *(uint4*)(sBh + so) = *(const uint4*)(Bgh + go);
            *(uint4*)(sBl + so) = *(const uint4*)(Bgl + go);
        }
        __syncthreads();
        #pragma unroll
        for (int ks = 0; ks < 4; ks++) {
            uint32_t ah[2][4], al[2][4], bh[8][2], bl[8][2];
            #pragma unroll
            for (int mf = 0; mf < 2; mf++) {
                uint32_t off = (uint32_t)(((wm + mf * 16 + a_row) * ASTR + ks * 16 + a_k) * 2);
                ldm_x4(ah[mf], uAh + off);
                ldm_x4(al[mf], uAl + off);
            }
            #pragma unroll
            for (int j = 0; j < 4; j++) {
                uint32_t off = (uint32_t)(((wn + j * 16 + b_row) * ASTR + ks * 16 + b_k) * 2);
                uint32_t r[4];
                ldm_x4(r, uBh + off);
                bh[2 * j][0] = r[0]; bh[2 * j][1] = r[1];
                bh[2 * j + 1][0] = r[2]; bh[2 * j + 1][1] = r[3];
                ldm_x4(r, uBl + off);
                bl[2 * j][0] = r[0]; bl[2 * j][1] = r[1];
                bl[2 * j + 1][0] = r[2]; bl[2 * j + 1][1] = r[3];
            }
            #pragma unroll
            for (int mf = 0; mf < 2; mf++)
                #pragma unroll
                for (int nf = 0; nf < 8; nf++) {
                    mma_bf16(acc[mf][nf], ah[mf], bh[nf]);
                    mma_bf16(acc[mf][nf], ah[mf], bl[nf]);
                    mma_bf16(acc[mf][nf], al[mf], bh[nf]);
                }
        }
        __syncthreads();
    }
    const int gq = lane >> 2, t2 = (lane & 3) * 2;
    #pragma unroll
    for (int mf = 0; mf < 2; mf++) {
        const int row = m0 + wm + mf * 16 + gq;
        #pragma unroll
        for (int nf = 0; nf < 8; nf++) {
            const int col = n0 + wn + nf * 8 + t2;
            float2 v0, v1;
            v0.x = silu_f(acc[mf][nf][0]);
            v0.y = silu_f(acc[mf][nf][1]);
            v1.x = silu_f(acc[mf][nf][2]);
            v1.y = silu_f(acc[mf][nf][3]);
            *(float2*)(C + (size_t)row * D + col) = v0;
            *(float2*)(C + (size_t)(row + 8) * D + col) = v1;
        }
    }
}

// ---------------- zero init for M, S ----------------------------------------
__global__ __launch_bounds__(256) void zero_kernel(float* __restrict__ M, float* __restrict__ S)
{
    int idx = blockIdx.x * 256 + threadIdx.x;
    float4 z = make_float4(0.f, 0.f, 0.f, 0.f);
    ((float4*)M)[idx] = z;
    ((float4*)S)[idx] = z;
}

// ---------------- l2norm + bf16 split of K and Q -----------------------------
__global__ __launch_bounds__(256) void l2norm_kernel(
    float* __restrict__ Kp, const float* __restrict__ Qp,
    __nv_bfloat16* __restrict__ Kh, __nv_bfloat16* __restrict__ Kl,
    __nv_bfloat16* __restrict__ Qh, __nv_bfloat16* __restrict__ Ql)
{
    const bool isK = (blockIdx.y == 0);
    const float* P = isK ? Kp : Qp;
    size_t base = (size_t)blockIdx.x * D + threadIdx.x * 4;
    float4 v = *(const float4*)(P + base);
    float ss = v.x * v.x + v.y * v.y + v.z * v.z + v.w * v.w;
    #pragma unroll
    for (int o = 16; o > 0; o >>= 1) ss += __shfl_xor_sync(0xffffffffu, ss, o);
    __shared__ float ws[8];
    if ((threadIdx.x & 31) == 0) ws[threadIdx.x >> 5] = ss;
    __syncthreads();
    float tot = 0.f;
    #pragma unroll
    for (int i = 0; i < 8; i++) tot += ws[i];
    float sc = 1.0f / (sqrtf(tot) + 1e-8f);
    v.x *= sc; v.y *= sc; v.z *= sc; v.w *= sc;
    if (isK) *(float4*)(Kp + base) = v;       // fp32 K needed for alpha
    __nv_bfloat16* H = isK ? Kh : Qh;
    __nv_bfloat16* L = isK ? Kl : Ql;
    __nv_bfloat16 h0 = __float2bfloat16(v.x);
    __nv_bfloat16 h1 = __float2bfloat16(v.y);
    __nv_bfloat16 h2 = __float2bfloat16(v.z);
    __nv_bfloat16 h3 = __float2bfloat16(v.w);
    ushort4 HH, LL;
    HH.x = __bfloat16_as_ushort(h0); HH.y = __bfloat16_as_ushort(h1);
    HH.z = __bfloat16_as_ushort(h2); HH.w = __bfloat16_as_ushort(h3);
    LL.x = __bfloat16_as_ushort(__float2bfloat16(v.x - __bfloat162float(h0)));
    LL.y = __bfloat16_as_ushort(__float2bfloat16(v.y - __bfloat162float(h1)));
    LL.z = __bfloat16_as_ushort(__float2bfloat16(v.z - __bfloat162float(h2)));
    LL.w = __bfloat16_as_ushort(__float2bfloat16(v.w - __bfloat162float(h3)));
    *(ushort4*)(H + base) = HH;
    *(ushort4*)(L + base) = LL;
}

// ---------------- per-chunk forgetting gate: alpha[c] ------------------------
__global__ __launch_bounds__(256) void alpha_kernel(
    const float* __restrict__ Kp, const float* __restrict__ Wf, float* __restrict__ alpha)
{
    const int c = blockIdx.x, t = threadIdx.x;
    float4 wf = *(const float4*)(Wf + t * 4);
    const float* Kc = Kp + (size_t)c * CSZ * D;
    float s = 0.f;
    #pragma unroll 4
    for (int r = 0; r < CSZ; r++) {
        float4 kv = *(const float4*)(Kc + (size_t)r * D + t * 4);
        s += kv.x * wf.x + kv.y * wf.y + kv.z * wf.z + kv.w * wf.w;
    }
    #pragma unroll
    for (int o = 16; o > 0; o >>= 1) s += __shfl_xor_sync(0xffffffffu, s, o);
    __shared__ float ws[8];
    if ((t & 31) == 0) ws[t >> 5] = s;
    __syncthreads();
    if (t == 0) {
        float tot = 0.f;
        #pragma unroll
        for (int i = 0; i < 8; i++) tot += ws[i];
        float mean = tot * (1.0f / CSZ);
        alpha[c] = 0.1f / (1.0f + __expf(-mean));
    }
}

// ---------------- HMMA state update: grad = Kc^T @ err; S,M update ----------
// grid (8 jt, 16 it), 256 thr, block tile 64i x 128j, warp 16i x 64j.
// A = K^T via trans-ldmatrix from [r][i] smem; B = err via trans from [r][j].
// Epilogue writes S,M fp32 and Mh/Ml bf16 splits.
#define USTR_K 72
#define USTR_E 136
__global__ __launch_bounds__(256) void update_mma(
    const __nv_bfloat16* __restrict__ Kh, const __nv_bfloat16* __restrict__ Kl,
    const __nv_bfloat16* __restrict__ Eh, const __nv_bfloat16* __restrict__ El,
    const float* __restrict__ alpha, float* __restrict__ M, float* __restrict__ S,
    __nv_bfloat16* __restrict__ Mh, __nv_bfloat16* __restrict__ Ml, int c, float errscale)
{
    extern __shared__ __nv_bfloat16 sm[];
    __nv_bfloat16* sKh = sm;
    __nv_bfloat16* sKl = sm + 128 * USTR_K;
    __nv_bfloat16* sEh = sm + 2 * 128 * USTR_K;
    __nv_bfloat16* sEl = sm + 2 * 128 * USTR_K + 128 * USTR_E;
    const int t = threadIdx.x, w = t >> 5, lane = t & 31;
    const int j0 = blockIdx.x * 128, i0 = blockIdx.y * 64;
    const __nv_bfloat16* Kch = Kh + (size_t)c * CSZ * D;
    const __nv_bfloat16* Kcl = Kl + (size_t)c * CSZ * D;

    #pragma unroll
    for (int i = 0; i < 4; i++) {
        int idx = t + i * 256; int row = idx >> 3, q = idx & 7;
        *(uint4*)(sKh + row * USTR_K + q * 8) = *(const uint4*)(Kch + (size_t)row * D + i0 + q * 8);
        *(uint4*)(sKl + row * USTR_K + q * 8) = *(const uint4*)(Kcl + (size_t)row * D + i0 + q * 8);
    }
    #pragma unroll
    for (int i = 0; i < 8; i++) {
        int idx = t + i * 256; int row = idx >> 4, q = idx & 15;
        *(uint4*)(sEh + row * USTR_E + q * 8) = *(const uint4*)(Eh + (size_t)row * D + j0 + q * 8);
        *(uint4*)(sEl + row * USTR_E + q * 8) = *(const uint4*)(El + (size_t)row * D + j0 + q * 8);
    }
    __syncthreads();

    const int wi0 = (w & 3) * 16, wj0 = (w >> 2) * 64;
    const int lt = lane >> 3, lr8 = lane & 7;
    const int a_r = (lt >> 1) * 8 + lr8, a_i = (lt & 1) * 8;   // A=K^T trans mapping
    const int b_k = (lt & 1) * 8 + lr8, b_n = (lt >> 1) * 8;   // B trans mapping
    const uint32_t uKh = smem_u32(sKh), uKl = smem_u32(sKl);
    const uint32_t uEh = smem_u32(sEh), uEl = smem_u32(sEl);

    float acc[8][4] = {};
    #pragma unroll
    for (int rs = 0; rs < 8; rs++) {
        uint32_t ah[4], al[4], bh[8][2], bl[8][2];
        uint32_t aoff = (uint32_t)(((rs * 16 + a_r) * USTR_K + wi0 + a_i) * 2);
        ldm_x4_t(ah, uKh + aoff);
        ldm_x4_t(al, uKl + aoff);
        #pragma unroll
        for (int jg = 0; jg < 4; jg++) {
            uint32_t boff = (uint32_t)(((rs * 16 + b_k) * USTR_E + wj0 + jg * 16 + b_n) * 2);
            uint32_t r[4];
            ldm_x4_t(r, uEh + boff);
            bh[2 * jg][0] = r[0]; bh[2 * jg][1] = r[1];
            bh[2 * jg + 1][0] = r[2]; bh[2 * jg + 1][1] = r[3];
            ldm_x4_t(r, uEl + boff);
            bl[2 * jg][0] = r[0]; bl[2 * jg][1] = r[1];
            bl[2 * jg + 1][0] = r[2]; bl[2 * jg + 1][1] = r[3];
        }
        #pragma unroll
        for (int nf = 0; nf < 8; nf++) {
            mma_bf16(acc[nf], ah, bh[nf]);
            mma_bf16(acc[nf], ah, bl[nf]);
            mma_bf16(acc[nf], al, bh[nf]);
        }
    }
    const float alp = alpha[c];
    const float oma = 1.0f - alp;
    const float gs = errscale * (0.01f / CSZ);
    const int gq = lane >> 2, t2 = (lane & 3) * 2;
    #pragma unroll
    for (int nf = 0; nf < 8; nf++) {
        #pragma unroll
        for (int h = 0; h < 2; h++) {
            int row = i0 + wi0 + gq + h * 8;
            int col = j0 + wj0 + nf * 8 + t2;
            size_t idx = (size_t)row * D + col;
            float2 s = *(float2*)(S + idx);
            float2 m = *(float2*)(M + idx);
            s.x = 0.9f * s.x - gs * acc[nf][h * 2 + 0];
            s.y = 0.9f * s.y - gs * acc[nf][h * 2 + 1];
            m.x = oma * m.x + s.x;
            m.y = oma * m.y + s.y;
            *(float2*)(S + idx) = s;
            *(float2*)(M + idx) = m;
            __nv_bfloat162 mh, ml;
            mh.x = __float2bfloat16(m.x); mh.y = __float2bfloat16(m.y);
            ml.x = __float2bfloat16(m.x - __bfloat162float(mh.x));
            ml.y = __float2bfloat16(m.y - __bfloat162float(mh.y));
            *(__nv_bfloat162*)(Mh + idx) = mh;
            *(__nv_bfloat162*)(Ml + idx) = ml;
        }
    }
}

// ---------------- HMMA retrieval + next-chunk error --------------------------
// grid (8 nt, mt: 0-3 Q / 4-7 K), 128 thr (4 warps 2m x 2n), tile 32m x 128n.
// A = Q or K rows (normal ldmatrix); B = M via trans-ldmatrix from Mh/Ml.
#define OSTR 136
__global__ __launch_bounds__(128) void outerr_mma(
    const __nv_bfloat16* __restrict__ Qh, const __nv_bfloat16* __restrict__ Ql,
    const __nv_bfloat16* __restrict__ Kh, const __nv_bfloat16* __restrict__ Kl,
    const float* __restrict__ Vp,
    const __nv_bfloat16* __restrict__ Mh, const __nv_bfloat16* __restrict__ Ml,
    float* __restrict__ out, __nv_bfloat16* __restrict__ errh, __nv_bfloat16* __restrict__ errl,
    int c)
{
    extern __shared__ __nv_bfloat16 sm[];
    __nv_bfloat16* sAh = sm;
    __nv_bfloat16* sAl = sm + 32 * OSTR;
    __nv_bfloat16* sBh = sm + 64 * OSTR;
    __nv_bfloat16* sBl = sm + 64 * OSTR + 128 * OSTR;
    const int t = threadIdx.x, w = t >> 5, lane = t & 31;
    const int n0 = blockIdx.x * 128;
    const int mt = blockIdx.y;
    const bool isQ = (mt < 4);
    const __nv_bfloat16* Agh = isQ ? (Qh + ((size_t)c * CSZ + mt * 32) * D)
                                   : (Kh + ((size_t)(c + 1) * CSZ + (mt - 4) * 32) * D);
    const __nv_bfloat16* Agl = isQ ? (Ql + ((size_t)c * CSZ + mt * 32) * D)
                                   : (Kl + ((size_t)(c + 1) * CSZ + (mt - 4) * 32) * D);
    const int wm = (w & 1) * 16, wn = (w >> 1) * 64;
    const int lt = lane >> 3, lr8 = lane & 7;
    const int a_m = (lt & 1) * 8 + lr8, a_k = (lt >> 1) * 8;   // A normal mapping
    const int b_k = (lt & 1) * 8 + lr8, b_n = (lt >> 1) * 8;   // B trans mapping
    const uint32_t uAh = smem_u32(sAh), uAl = smem_u32(sAl);
    const uint32_t uBh = smem_u32(sBh), uBl = smem_u32(sBl);

    float acc[8][4] = {};
    for (int kc = 0; kc < 8; kc++) {
        __syncthreads();
        #pragma unroll
        for (int i = 0; i < 4; i++) {
            int idx = t + i * 128; int row = idx >> 4, q = idx & 15;
            *(uint4*)(sAh + row * OSTR + q * 8) = *(const uint4*)(Agh + (size_t)row * D + kc * 128 + q * 8);
            *(uint4*)(sAl + row * OSTR + q * 8) = *(const uint4*)(Agl + (size_t)row * D + kc * 128 + q * 8);
        }
        #pragma unroll
        for (int i = 0; i < 16; i++) {
            int idx = t + i * 128; int row = idx >> 4, q = idx & 15;
            *(uint4*)(sBh + row * OSTR + q * 8) = *(const uint4*)(Mh + (size_t)(kc * 128 + row) * D + n0 + q * 8);
            *(uint4*)(sBl + row * OSTR + q * 8) = *(const uint4*)(Ml + (size_t)(kc * 128 + row) * D + n0 + q * 8);
        }
        __syncthreads();
        #pragma unroll
        for (int ks = 0; ks < 8; ks++) {
            uint32_t ah[4], al[4], bh[8][2], bl[8][2];
            uint32_t aoff = (uint32_t)(((wm + a_m) * OSTR + ks * 16 + a_k) * 2);
            ldm_x4(ah, uAh + aoff);
            ldm_x4(al, uAl + aoff);
            #pragma unroll
            for (int jg = 0; jg < 4; jg++) {
                uint32_t boff = (uint32_t)(((ks * 16 + b_k) * OSTR + wn + jg * 16 + b_n) * 2);
                uint32_t r[4];
                ldm_x4_t(r, uBh + boff);
                bh[2 * jg][0] = r[0]; bh[2 * jg][1] = r[1];
                bh[2 * jg + 1][0] = r[2]; bh[2 * jg + 1][1] = r[3];
                ldm_x4_t(r, uBl + boff);
                bl[2 * jg][0] = r[0]; bl[2 * jg][1] = r[1];
                bl[2 * jg + 1][0] = r[2]; bl[2 * jg + 1][1] = r[3];
            }
            #pragma unroll
            for (int nf = 0; nf < 8; nf++) {
                mma_bf16(acc[nf], ah, bh[nf]);
                mma_bf16(acc[nf], ah, bl[nf]);
                mma_bf16(acc[nf], al, bh[nf]);
            }
        }
    }
    const int gq = lane >> 2, t2 = (lane & 3) * 2;
    if (isQ) {
        #pragma unroll
        for (int nf = 0; nf < 8; nf++)
            #pragma unroll
            for (int h = 0; h < 2; h++) {
                int row = c * CSZ + mt * 32 + wm + gq + h * 8;
                int col = n0 + wn + nf * 8 + t2;
                *(float2*)(out + (size_t)row * D + col) =
                    make_float2(acc[nf][h * 2], acc[nf][h * 2 + 1]);
            }
    } else {
        #pragma unroll
        for (int nf = 0; nf < 8; nf++)
            #pragma unroll
            for (int h = 0; h < 2; h++) {
                int rl = (mt - 4) * 32 + wm + gq + h * 8;
                int col = n0 + wn + nf * 8 + t2;
                float2 vv = *(const float2*)(Vp + ((size_t)(c + 1) * CSZ + rl) * D + col);
                float ex = acc[nf][h * 2] - vv.x;
                float ey = acc[nf][h * 2 + 1] - vv.y;
                __nv_bfloat162 hh, ll;
                hh.x = __float2bfloat16(ex);
                hh.y = __float2bfloat16(ey);
                ll.x = __float2bfloat16(ex - __bfloat162float(hh.x));
                ll.y = __float2bfloat16(ey - __bfloat162float(hh.y));
                *(__nv_bfloat162*)(errh + (size_t)rl * D + col) = hh;
                *(__nv_bfloat162*)(errl + (size_t)rl * D + col) = ll;
            }
    }
}

// ---------------- launcher ----------------------------------------------------
extern "C" void kernel_launch(void* const* d_in, const int* in_sizes, int n_in,
                              void* d_out, int out_size)
{
    const float* x  = (const float*)d_in[0];
    const float* Wk = (const float*)d_in[1];
    const float* Wv = (const float*)d_in[2];
    const float* Wq = (const float*)d_in[3];
    const float* Wf = (const float*)d_in[4];
    float* out = (float*)d_out;

    float *Kp, *Vp, *Qp, *Mp, *Sp, *alphap;
    __nv_bfloat16 *xh, *xl, *Wh, *Wl, *Khp, *Klp, *Qhp, *Qlp, *Mhp, *Mlp;
    __nv_bfloat16 *errhp, *errlp, *e0hp, *e0lp;
    cudaGetSymbolAddress((void**)&Kp, g_K);
    cudaGetSymbolAddress((void**)&Vp, g_V);
    cudaGetSymbolAddress((void**)&Qp, g_Q);
    cudaGetSymbolAddress((void**)&Mp, g_M);
    cudaGetSymbolAddress((void**)&Sp, g_S);
    cudaGetSymbolAddress((void**)&alphap, g_alpha);
    cudaGetSymbolAddress((void**)&xh, g_xh);
    cudaGetSymbolAddress((void**)&xl, g_xl);
    cudaGetSymbolAddress((void**)&Wh, g_Wh);
    cudaGetSymbolAddress((void**)&Wl, g_Wl);
    cudaGetSymbolAddress((void**)&Khp, g_Kh);
    cudaGetSymbolAddress((void**)&Klp, g_Kl);
    cudaGetSymbolAddress((void**)&Qhp, g_Qh);
    cudaGetSymbolAddress((void**)&Qlp, g_Ql);
    cudaGetSymbolAddress((void**)&Mhp, g_Mh);
    cudaGetSymbolAddress((void**)&Mlp, g_Ml);
    cudaGetSymbolAddress((void**)&errhp, g_errh);
    cudaGetSymbolAddress((void**)&errlp, g_errl);
    cudaGetSymbolAddress((void**)&e0hp, g_e0h);
    cudaGetSymbolAddress((void**)&e0lp, g_e0l);

    const int proj_smem = 4 * 128 * ASTR * 2;                        // 73728
    const int upd_smem  = (2 * 128 * USTR_K + 2 * 128 * USTR_E) * 2; // 106496
    const int oer_smem  = (64 * OSTR + 2 * 128 * OSTR) * 2;          // 87040
    cudaFuncSetAttribute(projmma_kernel, cudaFuncAttributeMaxDynamicSharedMemorySize, proj_smem);
    cudaFuncSetAttribute(update_mma, cudaFuncAttributeMaxDynamicSharedMemorySize, upd_smem);
    cudaFuncSetAttribute(outerr_mma, cudaFuncAttributeMaxDynamicSharedMemorySize, oer_smem);

    // Parallel phase.
    convert_kernel<<<SEQ_LEN * D / 1024, 256>>>(x, xh, xl);
    convert_kernel<<<D * D / 1024, 256>>>(Wk, Wh, Wl);
    convert_kernel<<<D * D / 1024, 256>>>(Wv, Wh + D * D, Wl + D * D);
    convert_kernel<<<D * D / 1024, 256>>>(Wq, Wh + 2 * D * D, Wl + 2 * D * D);
    projmma_kernel<<<dim3(SEQ_LEN / 128, D / 128, 3), 256, proj_smem>>>(
        xh, xl, Wh, Wl, Kp, Vp, Qp);
    l2norm_kernel<<<dim3(SEQ_LEN, 2), 256>>>(Kp, Qp, Khp, Klp, Qhp, Qlp);
    alpha_kernel<<<NCH, 256>>>(Kp, Wf, alphap);
    convert_kernel<<<CSZ * D / 1024, 256>>>(Vp, e0hp, e0lp);   // err_0 = -V_0 (sign via gs)
    zero_kernel<<<1024, 256>>>(Mp, Sp);

    // Sequential phase: 2 HMMA kernels per chunk.
    for (int c = 0; c < NCH; c++) {
        const __nv_bfloat16* eh = (c == 0) ? e0hp : errhp;
        const __nv_bfloat16* el = (c == 0) ? e0lp : errlp;
        float esc = (c == 0) ? -1.0f : 1.0f;
        update_mma<<<dim3(8, 16), 256, upd_smem>>>(Khp, Klp, eh, el, alphap,
                                                   Mp, Sp, Mhp, Mlp, c, esc);
        outerr_mma<<<dim3(8, (c < NCH - 1) ? 8 : 4), 128, oer_smem>>>(
            Qhp, Qlp, Khp, Klp, Vp, Mhp, Mlp, out, errhp, errlp, c);
    }
}

// round 8
// speedup vs baseline: 2.4489x; 1.7459x over previous
#include <cuda_runtime.h>
#include <cuda_bf16.h>
#include <math.h>
#include <cstdint>

#define SEQ_LEN 16384
#define D       1024
#define CSZ     128
#define NCH     128
#define NB      128

// ---------------- scratch (static device globals; no runtime allocs) --------
__device__ float g_K[(size_t)SEQ_LEN * D];
__device__ float g_V[(size_t)SEQ_LEN * D];
__device__ float g_Q[(size_t)SEQ_LEN * D];
__device__ float g_M[D * D];
__device__ float g_S[D * D];
__device__ float g_alpha[NCH];
__device__ __nv_bfloat16 g_xh[(size_t)SEQ_LEN * D];
__device__ __nv_bfloat16 g_xl[(size_t)SEQ_LEN * D];
__device__ __nv_bfloat16 g_Wh[3 * D * D];
__device__ __nv_bfloat16 g_Wl[3 * D * D];
__device__ __nv_bfloat16 g_Kh[(size_t)SEQ_LEN * D];
__device__ __nv_bfloat16 g_Kl[(size_t)SEQ_LEN * D];
__device__ __nv_bfloat16 g_Qh[(size_t)SEQ_LEN * D];
__device__ __nv_bfloat16 g_Ql[(size_t)SEQ_LEN * D];
__device__ __nv_bfloat16 g_Mh[D * D];
__device__ __nv_bfloat16 g_Ml[D * D];
__device__ __nv_bfloat16 g_errh[CSZ * D];
__device__ __nv_bfloat16 g_errl[CSZ * D];
__device__ __nv_bfloat16 g_e0h[CSZ * D];
__device__ __nv_bfloat16 g_e0l[CSZ * D];
__device__ unsigned g_cnt = 0;
__device__ volatile unsigned g_gen;

__device__ __forceinline__ float silu_f(float x) { return x / (1.0f + __expf(-x)); }

// ---------------- mma.sync helpers (baseline PTX, sm_80+) -------------------
__device__ __forceinline__ uint32_t smem_u32(const void* p) {
    uint32_t a;
    asm("{ .reg .u64 t; cvta.to.shared.u64 t, %1; cvt.u32.u64 %0, t; }" : "=r"(a) : "l"(p));
    return a;
}
__device__ __forceinline__ void ldm_x4(uint32_t* r, uint32_t addr) {
    asm volatile("ldmatrix.sync.aligned.m8n8.x4.shared.b16 {%0,%1,%2,%3}, [%4];"
                 : "=r"(r[0]), "=r"(r[1]), "=r"(r[2]), "=r"(r[3]) : "r"(addr));
}
__device__ __forceinline__ void ldm_x4_t(uint32_t* r, uint32_t addr) {
    asm volatile("ldmatrix.sync.aligned.m8n8.x4.trans.shared.b16 {%0,%1,%2,%3}, [%4];"
                 : "=r"(r[0]), "=r"(r[1]), "=r"(r[2]), "=r"(r[3]) : "r"(addr));
}
__device__ __forceinline__ void mma_bf16(float* c, const uint32_t* a, const uint32_t* b) {
    asm volatile("mma.sync.aligned.m16n8k16.row.col.f32.bf16.bf16.f32 "
                 "{%0,%1,%2,%3}, {%4,%5,%6,%7}, {%8,%9}, {%0,%1,%2,%3};"
                 : "+f"(c[0]), "+f"(c[1]), "+f"(c[2]), "+f"(c[3])
                 : "r"(a[0]), "r"(a[1]), "r"(a[2]), "r"(a[3]), "r"(b[0]), "r"(b[1]));
}

// ---------------- grid barrier: atomic arrive, volatile-load spin -----------
__device__ __forceinline__ void grid_sync() {
    __syncthreads();
    if (threadIdx.x == 0) {
        unsigned gen = g_gen;                      // volatile read (stable pre-release)
        __threadfence();
        unsigned a = atomicAdd(&g_cnt, 1u);
        if (a == NB - 1) {
            g_cnt = 0;
            __threadfence();
            g_gen = gen + 1;                       // volatile store (release)
        } else {
            while (g_gen == gen) { }               // plain L2 reads, no atomics
            __threadfence();
        }
    }
    __syncthreads();
}

// ---------------- fp32 -> bf16 hi/lo split -----------------------------------
__global__ __launch_bounds__(256) void convert_kernel(
    const float* __restrict__ src, __nv_bfloat16* __restrict__ hi, __nv_bfloat16* __restrict__ lo)
{
    int i = blockIdx.x * 256 + threadIdx.x;
    float4 v = ((const float4*)src)[i];
    __nv_bfloat16 h0 = __float2bfloat16(v.x);
    __nv_bfloat16 h1 = __float2bfloat16(v.y);
    __nv_bfloat16 h2 = __float2bfloat16(v.z);
    __nv_bfloat16 h3 = __float2bfloat16(v.w);
    ushort4 H, L;
    H.x = __bfloat16_as_ushort(h0); H.y = __bfloat16_as_ushort(h1);
    H.z = __bfloat16_as_ushort(h2); H.w = __bfloat16_as_ushort(h3);
    L.x = __bfloat16_as_ushort(__float2bfloat16(v.x - __bfloat162float(h0)));
    L.y = __bfloat16_as_ushort(__float2bfloat16(v.y - __bfloat162float(h1)));
    L.z = __bfloat16_as_ushort(__float2bfloat16(v.z - __bfloat162float(h2)));
    L.w = __bfloat16_as_ushort(__float2bfloat16(v.w - __bfloat162float(h3)));
    ((ushort4*)hi)[i] = H;
    ((ushort4*)lo)[i] = L;
}

// ---------------- HMMA projection GEMM: C = silu(A @ W^T) -------------------
#define ASTR 72
__global__ __launch_bounds__(256) void projmma_kernel(
    const __nv_bfloat16* __restrict__ xh, const __nv_bfloat16* __restrict__ xl,
    const __nv_bfloat16* __restrict__ Wh3, const __nv_bfloat16* __restrict__ Wl3,
    float* __restrict__ Ko, float* __restrict__ Vo, float* __restrict__ Qo)
{
    extern __shared__ __nv_bfloat16 smbf[];
    __nv_bfloat16* sAh = smbf;
    __nv_bfloat16* sAl = smbf + 128 * ASTR;
    __nv_bfloat16* sBh = smbf + 2 * 128 * ASTR;
    __nv_bfloat16* sBl = smbf + 3 * 128 * ASTR;

    const int t = threadIdx.x;
    const int w = t >> 5, lane = t & 31;
    const int m0 = blockIdx.x * 128, n0 = blockIdx.y * 128;
    const int g = blockIdx.z;
    const __nv_bfloat16* Agh = xh + (size_t)m0 * D;
    const __nv_bfloat16* Agl = xl + (size_t)m0 * D;
    const __nv_bfloat16* Bgh = Wh3 + (size_t)g * D * D + (size_t)n0 * D;
    const __nv_bfloat16* Bgl = Wl3 + (size_t)g * D * D + (size_t)n0 * D;
    float* C = (g == 0) ? Ko : ((g == 1) ? Vo : Qo);

    const int wm = (w & 3) * 32, wn = (w >> 2) * 64;

    float acc[2][8][4];
    #pragma unroll
    for (int i = 0; i < 2; i++)
        #pragma unroll
        for (int j = 0; j < 8; j++)
            #pragma unroll
            for (int q = 0; q < 4; q++) acc[i][j][q] = 0.f;

    const int lt = lane >> 3, lr8 = lane & 7;
    const int a_row = (lt & 1) * 8 + lr8;
    const int a_k   = (lt >> 1) * 8;
    const int b_row = (lt >> 1) * 8 + lr8;
    const int b_k   = (lt & 1) * 8;

    const uint32_t uAh = smem_u32(sAh), uAl = smem_u32(sAl);
    const uint32_t uBh = smem_u32(sBh), uBl = smem_u32(sBl);

    for (int kc = 0; kc < 16; kc++) {
        #pragma unroll
        for (int i = 0; i < 4; i++) {
            int idx = t + i * 256;
            int row = idx >> 3, c8 = (idx & 7) * 8;
            size_t go = (size_t)row * D + kc * 64 + c8;
            int so = row * ASTR + c8;
            *(uint4*)(sAh + so) = *(const uint4*)(Agh + go);
            *(uint4*)(sAl + so) = *(const uint4*)(Agl + go);
            *(uint4*)(sBh + so) = *(const uint4*)(Bgh + go);
            *(uint4*)(sBl + so) = *(const uint4*)(Bgl + go);
        }
        __syncthreads();
        #pragma unroll
        for (int ks = 0; ks < 4; ks++) {
            uint32_t ah[2][4], al[2][4], bh[8][2], bl[8][2];
            #pragma unroll
            for (int mf = 0; mf < 2; mf++) {
                uint32_t off = (uint32_t)(((wm + mf * 16 + a_row) * ASTR + ks * 16 + a_k) * 2);
                ldm_x4(ah[mf], uAh + off);
                ldm_x4(al[mf], uAl + off);
            }
            #pragma unroll
            for (int j = 0; j < 4; j++) {
                uint32_t off = (uint32_t)(((wn + j * 16 + b_row) * ASTR + ks * 16 + b_k) * 2);
                uint32_t r[4];
                ldm_x4(r, uBh + off);
                bh[2 * j][0] = r[0]; bh[2 * j][1] = r[1];
                bh[2 * j + 1][0] = r[2]; bh[2 * j + 1][1] = r[3];
                ldm_x4(r, uBl + off);
                bl[2 * j][0] = r[0]; bl[2 * j][1] = r[1];
                bl[2 * j + 1][0] = r[2]; bl[2 * j + 1][1] = r[3];
            }
            #pragma unroll
            for (int mf = 0; mf < 2; mf++)
                #pragma unroll
                for (int nf = 0; nf < 8; nf++) {
                    mma_bf16(acc[mf][nf], ah[mf], bh[nf]);
                    mma_bf16(acc[mf][nf], ah[mf], bl[nf]);
                    mma_bf16(acc[mf][nf], al[mf], bh[nf]);
                }
        }
        __syncthreads();
    }
    const int gq = lane >> 2, t2 = (lane & 3) * 2;
    #pragma unroll
    for (int mf = 0; mf < 2; mf++) {
        const int row = m0 + wm + mf * 16 + gq;
        #pragma unroll
        for (int nf = 0; nf < 8; nf++) {
            const int col = n0 + wn + nf * 8 + t2;
            float2 v0, v1;
            v0.x = silu_f(acc[mf][nf][0]);
            v0.y = silu_f(acc[mf][nf][1]);
            v1.x = silu_f(acc[mf][nf][2]);
            v1.y = silu_f(acc[mf][nf][3]);
            *(float2*)(C + (size_t)row * D + col) = v0;
            *(float2*)(C + (size_t)(row + 8) * D + col) = v1;
        }
    }
}

// ---------------- l2norm + bf16 split of K and Q -----------------------------
__global__ __launch_bounds__(256) void l2norm_kernel(
    float* __restrict__ Kp, const float* __restrict__ Qp,
    __nv_bfloat16* __restrict__ Kh, __nv_bfloat16* __restrict__ Kl,
    __nv_bfloat16* __restrict__ Qh, __nv_bfloat16* __restrict__ Ql)
{
    const bool isK = (blockIdx.y == 0);
    const float* P = isK ? Kp : Qp;
    size_t base = (size_t)blockIdx.x * D + threadIdx.x * 4;
    float4 v = *(const float4*)(P + base);
    float ss = v.x * v.x + v.y * v.y + v.z * v.z + v.w * v.w;
    #pragma unroll
    for (int o = 16; o > 0; o >>= 1) ss += __shfl_xor_sync(0xffffffffu, ss, o);
    __shared__ float ws[8];
    if ((threadIdx.x & 31) == 0) ws[threadIdx.x >> 5] = ss;
    __syncthreads();
    float tot = 0.f;
    #pragma unroll
    for (int i = 0; i < 8; i++) tot += ws[i];
    float sc = 1.0f / (sqrtf(tot) + 1e-8f);
    v.x *= sc; v.y *= sc; v.z *= sc; v.w *= sc;
    if (isK) *(float4*)(Kp + base) = v;
    __nv_bfloat16* H = isK ? Kh : Qh;
    __nv_bfloat16* L = isK ? Kl : Ql;
    __nv_bfloat16 h0 = __float2bfloat16(v.x);
    __nv_bfloat16 h1 = __float2bfloat16(v.y);
    __nv_bfloat16 h2 = __float2bfloat16(v.z);
    __nv_bfloat16 h3 = __float2bfloat16(v.w);
    ushort4 HH, LL;
    HH.x = __bfloat16_as_ushort(h0); HH.y = __bfloat16_as_ushort(h1);
    HH.z = __bfloat16_as_ushort(h2); HH.w = __bfloat16_as_ushort(h3);
    LL.x = __bfloat16_as_ushort(__float2bfloat16(v.x - __bfloat162float(h0)));
    LL.y = __bfloat16_as_ushort(__float2bfloat16(v.y - __bfloat162float(h1)));
    LL.z = __bfloat16_as_ushort(__float2bfloat16(v.z - __bfloat162float(h2)));
    LL.w = __bfloat16_as_ushort(__float2bfloat16(v.w - __bfloat162float(h3)));
    *(ushort4*)(H + base) = HH;
    *(ushort4*)(L + base) = LL;
}

// ---------------- per-chunk forgetting gate: alpha[c] ------------------------
__global__ __launch_bounds__(256) void alpha_kernel(
    const float* __restrict__ Kp, const float* __restrict__ Wf, float* __restrict__ alpha)
{
    const int c = blockIdx.x, t = threadIdx.x;
    float4 wf = *(const float4*)(Wf + t * 4);
    const float* Kc = Kp + (size_t)c * CSZ * D;
    float s = 0.f;
    #pragma unroll 4
    for (int r = 0; r < CSZ; r++) {
        float4 kv = *(const float4*)(Kc + (size_t)r * D + t * 4);
        s += kv.x * wf.x + kv.y * wf.y + kv.z * wf.z + kv.w * wf.w;
    }
    #pragma unroll
    for (int o = 16; o > 0; o >>= 1) s += __shfl_xor_sync(0xffffffffu, s, o);
    __shared__ float ws[8];
    if ((t & 31) == 0) ws[t >> 5] = s;
    __syncthreads();
    if (t == 0) {
        float tot = 0.f;
        #pragma unroll
        for (int i = 0; i < 8; i++) tot += ws[i];
        float mean = tot * (1.0f / CSZ);
        alpha[c] = 0.1f / (1.0f + __expf(-mean));
    }
}

// ---------------- persistent sequential kernel (HMMA phases) ----------------
#define USTR_K 72
#define USTR_E 136
#define OSTR   136
__global__ __launch_bounds__(256, 1) void titan_seq(
    const __nv_bfloat16* __restrict__ Kh, const __nv_bfloat16* __restrict__ Kl,
    const __nv_bfloat16* __restrict__ Qh, const __nv_bfloat16* __restrict__ Ql,
    const __nv_bfloat16* __restrict__ e0h, const __nv_bfloat16* __restrict__ e0l,
    __nv_bfloat16* __restrict__ errh, __nv_bfloat16* __restrict__ errl,
    const float* __restrict__ Vp, const float* __restrict__ alpha,
    float* __restrict__ M, float* __restrict__ S,
    __nv_bfloat16* __restrict__ Mh, __nv_bfloat16* __restrict__ Ml,
    float* __restrict__ out)
{
    extern __shared__ __nv_bfloat16 sm[];
    const int t = threadIdx.x, w = t >> 5, lane = t & 31;
    const int b = blockIdx.x;
    const int lt = lane >> 3, lr8 = lane & 7;
    const int gq = lane >> 2, t2 = (lane & 3) * 2;

    // zero-init M, S
    {
        float4 z = make_float4(0.f, 0.f, 0.f, 0.f);
        for (int idx = b * 256 + t; idx < D * D / 4; idx += NB * 256) {
            ((float4*)M)[idx] = z;
            ((float4*)S)[idx] = z;
        }
    }
    grid_sync();

    for (int c = 0; c < NCH; c++) {
        // ================= update phase: grad = Kc^T @ err; S,M; Mh/Ml ======
        {
            __nv_bfloat16* sKh = sm;
            __nv_bfloat16* sKl = sm + 128 * USTR_K;
            __nv_bfloat16* sEh = sm + 2 * 128 * USTR_K;
            __nv_bfloat16* sEl = sm + 2 * 128 * USTR_K + 128 * USTR_E;
            const int j0 = (b & 7) * 128, i0 = (b >> 3) * 64;
            const __nv_bfloat16* Kch = Kh + (size_t)c * CSZ * D;
            const __nv_bfloat16* Kcl = Kl + (size_t)c * CSZ * D;
            const __nv_bfloat16* Eh = (c == 0) ? e0h : errh;
            const __nv_bfloat16* El = (c == 0) ? e0l : errl;

            #pragma unroll
            for (int i = 0; i < 4; i++) {
                int idx = t + i * 256; int row = idx >> 3, q = idx & 7;
                *(uint4*)(sKh + row * USTR_K + q * 8) = *(const uint4*)(Kch + (size_t)row * D + i0 + q * 8);
                *(uint4*)(sKl + row * USTR_K + q * 8) = *(const uint4*)(Kcl + (size_t)row * D + i0 + q * 8);
            }
            #pragma unroll
            for (int i = 0; i < 8; i++) {
                int idx = t + i * 256; int row = idx >> 4, q = idx & 15;
                *(uint4*)(sEh + row * USTR_E + q * 8) = *(const uint4*)(Eh + (size_t)row * D + j0 + q * 8);
                *(uint4*)(sEl + row * USTR_E + q * 8) = *(const uint4*)(El + (size_t)row * D + j0 + q * 8);
            }
            __syncthreads();

            const int wi0 = (w & 3) * 16, wj0 = (w >> 2) * 64;
            const int a_r = (lt >> 1) * 8 + lr8, a_i = (lt & 1) * 8;
            const int b_k = (lt & 1) * 8 + lr8, b_n = (lt >> 1) * 8;
            const uint32_t uKh = smem_u32(sKh), uKl = smem_u32(sKl);
            const uint32_t uEh = smem_u32(sEh), uEl = smem_u32(sEl);

            float acc[8][4] = {};
            #pragma unroll
            for (int rs = 0; rs < 8; rs++) {
                uint32_t ah[4], al[4], bh[8][2], bl[8][2];
                uint32_t aoff = (uint32_t)(((rs * 16 + a_r) * USTR_K + wi0 + a_i) * 2);
                ldm_x4_t(ah, uKh + aoff);
                ldm_x4_t(al, uKl + aoff);
                #pragma unroll
                for (int jg = 0; jg < 4; jg++) {
                    uint32_t boff = (uint32_t)(((rs * 16 + b_k) * USTR_E + wj0 + jg * 16 + b_n) * 2);
                    uint32_t r[4];
                    ldm_x4_t(r, uEh + boff);
                    bh[2 * jg][0] = r[0]; bh[2 * jg][1] = r[1];
                    bh[2 * jg + 1][0] = r[2]; bh[2 * jg + 1][1] = r[3];
                    ldm_x4_t(r, uEl + boff);
                    bl[2 * jg][0] = r[0]; bl[2 * jg][1] = r[1];
                    bl[2 * jg + 1][0] = r[2]; bl[2 * jg + 1][1] = r[3];
                }
                #pragma unroll
                for (int nf = 0; nf < 8; nf++) {
                    mma_bf16(acc[nf], ah, bh[nf]);
                    mma_bf16(acc[nf], ah, bl[nf]);
                    mma_bf16(acc[nf], al, bh[nf]);
                }
            }
            const float alp = alpha[c];
            const float oma = 1.0f - alp;
            const float gs = ((c == 0) ? -1.0f : 1.0f) * (0.01f / CSZ);
            #pragma unroll
            for (int nf = 0; nf < 8; nf++) {
                #pragma unroll
                for (int h = 0; h < 2; h++) {
                    int row = i0 + wi0 + gq + h * 8;
                    int col = j0 + wj0 + nf * 8 + t2;
                    size_t idx = (size_t)row * D + col;
                    float2 s = *(float2*)(S + idx);
                    float2 m = *(float2*)(M + idx);
                    s.x = 0.9f * s.x - gs * acc[nf][h * 2 + 0];
                    s.y = 0.9f * s.y - gs * acc[nf][h * 2 + 1];
                    m.x = oma * m.x + s.x;
                    m.y = oma * m.y + s.y;
                    *(float2*)(S + idx) = s;
                    *(float2*)(M + idx) = m;
                    __nv_bfloat162 mh, ml;
                    mh.x = __float2bfloat16(m.x); mh.y = __float2bfloat16(m.y);
                    ml.x = __float2bfloat16(m.x - __bfloat162float(mh.x));
                    ml.y = __float2bfloat16(m.y - __bfloat162float(mh.y));
                    *(__nv_bfloat162*)(Mh + idx) = mh;
                    *(__nv_bfloat162*)(Ml + idx) = ml;
                }
            }
        }
        grid_sync();

        // ================= outerr phase: out = Q@M; err' = K@M - V ==========
        if (b < 64) {
            const int mt = b >> 3;
            if (c < NCH - 1 || mt < 4) {
                __nv_bfloat16* sAh = sm;
                __nv_bfloat16* sAl = sm + 32 * OSTR;
                __nv_bfloat16* sBh = sm + 64 * OSTR;
                __nv_bfloat16* sBl = sm + 64 * OSTR + 128 * OSTR;
                const int n0 = (b & 7) * 128;
                const bool isQ = (mt < 4);
                const __nv_bfloat16* Agh = isQ ? (Qh + ((size_t)c * CSZ + mt * 32) * D)
                                               : (Kh + ((size_t)(c + 1) * CSZ + (mt - 4) * 32) * D);
                const __nv_bfloat16* Agl = isQ ? (Ql + ((size_t)c * CSZ + mt * 32) * D)
                                               : (Kl + ((size_t)(c + 1) * CSZ + (mt - 4) * 32) * D);
                const int wm = (w & 1) * 16, wn = ((w >> 1) & 1) * 64;  // warps 0-3 tile
                const int a_m = (lt & 1) * 8 + lr8, a_k = (lt >> 1) * 8;
                const int b_k = (lt & 1) * 8 + lr8, b_n = (lt >> 1) * 8;
                const uint32_t uAh = smem_u32(sAh), uAl = smem_u32(sAl);
                const uint32_t uBh = smem_u32(sBh), uBl = smem_u32(sBl);

                float acc[8][4] = {};
                for (int kc = 0; kc < 8; kc++) {
                    __syncthreads();
                    #pragma unroll
                    for (int i = 0; i < 2; i++) {            // 256 thr load A
                        int idx = t + i * 256; int row = idx >> 4, q = idx & 15;
                        *(uint4*)(sAh + row * OSTR + q * 8) =
                            *(const uint4*)(Agh + (size_t)row * D + kc * 128 + q * 8);
                        *(uint4*)(sAl + row * OSTR + q * 8) =
                            *(const uint4*)(Agl + (size_t)row * D + kc * 128 + q * 8);
                    }
                    #pragma unroll
                    for (int i = 0; i < 8; i++) {            // 256 thr load B
                        int idx = t + i * 256; int row = idx >> 4, q = idx & 15;
                        *(uint4*)(sBh + row * OSTR + q * 8) =
                            *(const uint4*)(Mh + (size_t)(kc * 128 + row) * D + n0 + q * 8);
                        *(uint4*)(sBl + row * OSTR + q * 8) =
                            *(const uint4*)(Ml + (size_t)(kc * 128 + row) * D + n0 + q * 8);
                    }
                    __syncthreads();
                    if (w < 4) {
                        #pragma unroll
                        for (int ks = 0; ks < 8; ks++) {
                            uint32_t ah[4], al[4], bh[8][2], bl[8][2];
                            uint32_t aoff = (uint32_t)(((wm + a_m) * OSTR + ks * 16 + a_k) * 2);
                            ldm_x4(ah, uAh + aoff);
                            ldm_x4(al, uAl + aoff);
                            #pragma unroll
                            for (int jg = 0; jg < 4; jg++) {
                                uint32_t boff = (uint32_t)(((ks * 16 + b_k) * OSTR + wn + jg * 16 + b_n) * 2);
                                uint32_t r[4];
                                ldm_x4_t(r, uBh + boff);
                                bh[2 * jg][0] = r[0]; bh[2 * jg][1] = r[1];
                                bh[2 * jg + 1][0] = r[2]; bh[2 * jg + 1][1] = r[3];
                                ldm_x4_t(r, uBl + boff);
                                bl[2 * jg][0] = r[0]; bl[2 * jg][1] = r[1];
                                bl[2 * jg + 1][0] = r[2]; bl[2 * jg + 1][1] = r[3];
                            }
                            #pragma unroll
                            for (int nf = 0; nf < 8; nf++) {
                                mma_bf16(acc[nf], ah, bh[nf]);
                                mma_bf16(acc[nf], ah, bl[nf]);
                                mma_bf16(acc[nf], al, bh[nf]);
                            }
                        }
                    }
                }
                if (w < 4) {
                    if (isQ) {
                        #pragma unroll
                        for (int nf = 0; nf < 8; nf++)
                            #pragma unroll
                            for (int h = 0; h < 2; h++) {
                                int row = c * CSZ + mt * 32 + wm + gq + h * 8;
                                int col = n0 + wn + nf * 8 + t2;
                                *(float2*)(out + (size_t)row * D + col) =
                                    make_float2(acc[nf][h * 2], acc[nf][h * 2 + 1]);
                            }
                    } else {
                        #pragma unroll
                        for (int nf = 0; nf < 8; nf++)
                            #pragma unroll
                            for (int h = 0; h < 2; h++) {
                                int rl = (mt - 4) * 32 + wm + gq + h * 8;
                                int col = n0 + wn + nf * 8 + t2;
                                float2 vv = *(const float2*)(Vp + ((size_t)(c + 1) * CSZ + rl) * D + col);
                                float ex = acc[nf][h * 2] - vv.x;
                                float ey = acc[nf][h * 2 + 1] - vv.y;
                                __nv_bfloat162 hh, ll;
                                hh.x = __float2bfloat16(ex);
                                hh.y = __float2bfloat16(ey);
                                ll.x = __float2bfloat16(ex - __bfloat162float(hh.x));
                                ll.y = __float2bfloat16(ey - __bfloat162float(hh.y));
                                *(__nv_bfloat162*)(errh + (size_t)rl * D + col) = hh;
                                *(__nv_bfloat162*)(errl + (size_t)rl * D + col) = ll;
                            }
                    }
                }
            }
        }
        grid_sync();
    }
}

// ---------------- launcher ----------------------------------------------------
extern "C" void kernel_launch(void* const* d_in, const int* in_sizes, int n_in,
                              void* d_out, int out_size)
{
    const float* x  = (const float*)d_in[0];
    const float* Wk = (const float*)d_in[1];
    const float* Wv = (const float*)d_in[2];
    const float* Wq = (const float*)d_in[3];
    const float* Wf = (const float*)d_in[4];
    float* out = (float*)d_out;

    float *Kp, *Vp, *Qp, *Mp, *Sp, *alphap;
    __nv_bfloat16 *xh, *xl, *Wh, *Wl, *Khp, *Klp, *Qhp, *Qlp, *Mhp, *Mlp;
    __nv_bfloat16 *errhp, *errlp, *e0hp, *e0lp;
    cudaGetSymbolAddress((void**)&Kp, g_K);
    cudaGetSymbolAddress((void**)&Vp, g_V);
    cudaGetSymbolAddress((void**)&Qp, g_Q);
    cudaGetSymbolAddress((void**)&Mp, g_M);
    cudaGetSymbolAddress((void**)&Sp, g_S);
    cudaGetSymbolAddress((void**)&alphap, g_alpha);
    cudaGetSymbolAddress((void**)&xh, g_xh);
    cudaGetSymbolAddress((void**)&xl, g_xl);
    cudaGetSymbolAddress((void**)&Wh, g_Wh);
    cudaGetSymbolAddress((void**)&Wl, g_Wl);
    cudaGetSymbolAddress((void**)&Khp, g_Kh);
    cudaGetSymbolAddress((void**)&Klp, g_Kl);
    cudaGetSymbolAddress((void**)&Qhp, g_Qh);
    cudaGetSymbolAddress((void**)&Qlp, g_Ql);
    cudaGetSymbolAddress((void**)&Mhp, g_Mh);
    cudaGetSymbolAddress((void**)&Mlp, g_Ml);
    cudaGetSymbolAddress((void**)&errhp, g_errh);
    cudaGetSymbolAddress((void**)&errlp, g_errl);
    cudaGetSymbolAddress((void**)&e0hp, g_e0h);
    cudaGetSymbolAddress((void**)&e0lp, g_e0l);

    const int proj_smem = 4 * 128 * ASTR * 2;                        // 73728
    const int seq_smem  = (2 * 128 * USTR_K + 2 * 128 * USTR_E) * 2; // 106496
    cudaFuncSetAttribute(projmma_kernel, cudaFuncAttributeMaxDynamicSharedMemorySize, proj_smem);
    cudaFuncSetAttribute(titan_seq, cudaFuncAttributeMaxDynamicSharedMemorySize, seq_smem);

    // Parallel phase.
    convert_kernel<<<SEQ_LEN * D / 1024, 256>>>(x, xh, xl);
    convert_kernel<<<D * D / 1024, 256>>>(Wk, Wh, Wl);
    convert_kernel<<<D * D / 1024, 256>>>(Wv, Wh + D * D, Wl + D * D);
    convert_kernel<<<D * D / 1024, 256>>>(Wq, Wh + 2 * D * D, Wl + 2 * D * D);
    projmma_kernel<<<dim3(SEQ_LEN / 128, D / 128, 3), 256, proj_smem>>>(
        xh, xl, Wh, Wl, Kp, Vp, Qp);
    l2norm_kernel<<<dim3(SEQ_LEN, 2), 256>>>(Kp, Qp, Khp, Klp, Qhp, Qlp);
    alpha_kernel<<<NCH, 256>>>(Kp, Wf, alphap);
    convert_kernel<<<CSZ * D / 1024, 256>>>(Vp, e0hp, e0lp);   // err_0 = -V_0 via gs sign

    // Sequential phase: ONE persistent kernel, HMMA phases, fast grid barrier.
    titan_seq<<<NB, 256, seq_smem>>>(Khp, Klp, Qhp, Qlp, e0hp, e0lp,
                                     errhp, errlp, Vp, alphap,
                                     Mp, Sp, Mhp, Mlp, out);
}

// round 9
// speedup vs baseline: 2.8114x; 1.1480x over previous
#include <cuda_runtime.h>
#include <cuda_bf16.h>
#include <math.h>
#include <cstdint>

#define SEQ_LEN 16384
#define D       1024
#define CSZ     128
#define NCH     128
#define NB      128

// ---------------- scratch (static device globals; no runtime allocs) --------
__device__ float g_K[(size_t)SEQ_LEN * D];
__device__ float g_V[(size_t)SEQ_LEN * D];
__device__ float g_Q[(size_t)SEQ_LEN * D];
__device__ float g_M[D * D];
__device__ float g_S[D * D];
__device__ float g_alpha[NCH];
__device__ __nv_bfloat16 g_xh[(size_t)SEQ_LEN * D];
__device__ __nv_bfloat16 g_xl[(size_t)SEQ_LEN * D];
__device__ __nv_bfloat16 g_Wh[3 * D * D];
__device__ __nv_bfloat16 g_Wl[3 * D * D];
__device__ __nv_bfloat16 g_Kh[(size_t)SEQ_LEN * D];
__device__ __nv_bfloat16 g_Kl[(size_t)SEQ_LEN * D];
__device__ __nv_bfloat16 g_Qh[(size_t)SEQ_LEN * D];
__device__ __nv_bfloat16 g_Ql[(size_t)SEQ_LEN * D];
__device__ __nv_bfloat16 g_Mh[D * D];
__device__ __nv_bfloat16 g_Ml[D * D];
__device__ __nv_bfloat16 g_errh[CSZ * D];
__device__ __nv_bfloat16 g_errl[CSZ * D];
__device__ __nv_bfloat16 g_e0h[CSZ * D];
__device__ __nv_bfloat16 g_e0l[CSZ * D];
__device__ unsigned g_cnt = 0;
__device__ volatile unsigned g_gen;

__device__ __forceinline__ float silu_f(float x) { return x / (1.0f + __expf(-x)); }

// ---------------- mma.sync helpers (baseline PTX, sm_80+) -------------------
__device__ __forceinline__ uint32_t smem_u32(const void* p) {
    uint32_t a;
    asm("{ .reg .u64 t; cvta.to.shared.u64 t, %1; cvt.u32.u64 %0, t; }" : "=r"(a) : "l"(p));
    return a;
}
__device__ __forceinline__ void ldm_x4(uint32_t* r, uint32_t addr) {
    asm volatile("ldmatrix.sync.aligned.m8n8.x4.shared.b16 {%0,%1,%2,%3}, [%4];"
                 : "=r"(r[0]), "=r"(r[1]), "=r"(r[2]), "=r"(r[3]) : "r"(addr));
}
__device__ __forceinline__ void ldm_x4_t(uint32_t* r, uint32_t addr) {
    asm volatile("ldmatrix.sync.aligned.m8n8.x4.trans.shared.b16 {%0,%1,%2,%3}, [%4];"
                 : "=r"(r[0]), "=r"(r[1]), "=r"(r[2]), "=r"(r[3]) : "r"(addr));
}
__device__ __forceinline__ void mma_bf16(float* c, const uint32_t* a, const uint32_t* b) {
    asm volatile("mma.sync.aligned.m16n8k16.row.col.f32.bf16.bf16.f32 "
                 "{%0,%1,%2,%3}, {%4,%5,%6,%7}, {%8,%9}, {%0,%1,%2,%3};"
                 : "+f"(c[0]), "+f"(c[1]), "+f"(c[2]), "+f"(c[3])
                 : "r"(a[0]), "r"(a[1]), "r"(a[2]), "r"(a[3]), "r"(b[0]), "r"(b[1]));
}

// ---------------- grid barrier: atomic arrive, volatile-load spin -----------
__device__ __forceinline__ void grid_sync() {
    __syncthreads();
    if (threadIdx.x == 0) {
        unsigned gen = g_gen;
        __threadfence();
        unsigned a = atomicAdd(&g_cnt, 1u);
        if (a == NB - 1) {
            g_cnt = 0;
            __threadfence();
            g_gen = gen + 1;
        } else {
            while (g_gen == gen) { }
            __threadfence();
        }
    }
    __syncthreads();
}

// ---------------- fp32 -> bf16 hi/lo split -----------------------------------
__global__ __launch_bounds__(256) void convert_kernel(
    const float* __restrict__ src, __nv_bfloat16* __restrict__ hi, __nv_bfloat16* __restrict__ lo)
{
    int i = blockIdx.x * 256 + threadIdx.x;
    float4 v = ((const float4*)src)[i];
    __nv_bfloat16 h0 = __float2bfloat16(v.x);
    __nv_bfloat16 h1 = __float2bfloat16(v.y);
    __nv_bfloat16 h2 = __float2bfloat16(v.z);
    __nv_bfloat16 h3 = __float2bfloat16(v.w);
    ushort4 H, L;
    H.x = __bfloat16_as_ushort(h0); H.y = __bfloat16_as_ushort(h1);
    H.z = __bfloat16_as_ushort(h2); H.w = __bfloat16_as_ushort(h3);
    L.x = __bfloat16_as_ushort(__float2bfloat16(v.x - __bfloat162float(h0)));
    L.y = __bfloat16_as_ushort(__float2bfloat16(v.y - __bfloat162float(h1)));
    L.z = __bfloat16_as_ushort(__float2bfloat16(v.z - __bfloat162float(h2)));
    L.w = __bfloat16_as_ushort(__float2bfloat16(v.w - __bfloat162float(h3)));
    ((ushort4*)hi)[i] = H;
    ((ushort4*)lo)[i] = L;
}

// ---------------- HMMA projection GEMM: C = silu(A @ W^T) -------------------
#define ASTR 72
__global__ __launch_bounds__(256) void projmma_kernel(
    const __nv_bfloat16* __restrict__ xh, const __nv_bfloat16* __restrict__ xl,
    const __nv_bfloat16* __restrict__ Wh3, const __nv_bfloat16* __restrict__ Wl3,
    float* __restrict__ Ko, float* __restrict__ Vo, float* __restrict__ Qo)
{
    extern __shared__ __nv_bfloat16 smbf[];
    __nv_bfloat16* sAh = smbf;
    __nv_bfloat16* sAl = smbf + 128 * ASTR;
    __nv_bfloat16* sBh = smbf + 2 * 128 * ASTR;
    __nv_bfloat16* sBl = smbf + 3 * 128 * ASTR;

    const int t = threadIdx.x;
    const int w = t >> 5, lane = t & 31;
    const int m0 = blockIdx.x * 128, n0 = blockIdx.y * 128;
    const int g = blockIdx.z;
    const __nv_bfloat16* Agh = xh + (size_t)m0 * D;
    const __nv_bfloat16* Agl = xl + (size_t)m0 * D;
    const __nv_bfloat16* Bgh = Wh3 + (size_t)g * D * D + (size_t)n0 * D;
    const __nv_bfloat16* Bgl = Wl3 + (size_t)g * D * D + (size_t)n0 * D;
    float* C = (g == 0) ? Ko : ((g == 1) ? Vo : Qo);

    const int wm = (w & 3) * 32, wn = (w >> 2) * 64;

    float acc[2][8][4];
    #pragma unroll
    for (int i = 0; i < 2; i++)
        #pragma unroll
        for (int j = 0; j < 8; j++)
            #pragma unroll
            for (int q = 0; q < 4; q++) acc[i][j][q] = 0.f;

    const int lt = lane >> 3, lr8 = lane & 7;
    const int a_row = (lt & 1) * 8 + lr8;
    const int a_k   = (lt >> 1) * 8;
    const int b_row = (lt >> 1) * 8 + lr8;
    const int b_k   = (lt & 1) * 8;

    const uint32_t uAh = smem_u32(sAh), uAl = smem_u32(sAl);
    const uint32_t uBh = smem_u32(sBh), uBl = smem_u32(sBl);

    for (int kc = 0; kc < 16; kc++) {
        #pragma unroll
        for (int i = 0; i < 4; i++) {
            int idx = t + i * 256;
            int row = idx >> 3, c8 = (idx & 7) * 8;
            size_t go = (size_t)row * D + kc * 64 + c8;
            int so = row * ASTR + c8;
            *(uint4*)(sAh + so) = *(const uint4*)(Agh + go);
            *(uint4*)(sAl + so) = *(const uint4*)(Agl + go);
            *(uint4*)(sBh + so) = *(const uint4*)(Bgh + go);
            *(uint4*)(sBl + so) = *(const uint4*)(Bgl + go);
        }
        __syncthreads();
        #pragma unroll
        for (int ks = 0; ks < 4; ks++) {
            uint32_t ah[2][4], al[2][4], bh[8][2], bl[8][2];
            #pragma unroll
            for (int mf = 0; mf < 2; mf++) {
                uint32_t off = (uint32_t)(((wm + mf * 16 + a_row) * ASTR + ks * 16 + a_k) * 2);
                ldm_x4(ah[mf], uAh + off);
                ldm_x4(al[mf], uAl + off);
            }
            #pragma unroll
            for (int j = 0; j < 4; j++) {
                uint32_t off = (uint32_t)(((wn + j * 16 + b_row) * ASTR + ks * 16 + b_k) * 2);
                uint32_t r[4];
                ldm_x4(r, uBh + off);
                bh[2 * j][0] = r[0]; bh[2 * j][1] = r[1];
                bh[2 * j + 1][0] = r[2]; bh[2 * j + 1][1] = r[3];
                ldm_x4(r, uBl + off);
                bl[2 * j][0] = r[0]; bl[2 * j][1] = r[1];
                bl[2 * j + 1][0] = r[2]; bl[2 * j + 1][1] = r[3];
            }
            #pragma unroll
            for (int mf = 0; mf < 2; mf++)
                #pragma unroll
                for (int nf = 0; nf < 8; nf++) {
                    mma_bf16(acc[mf][nf], ah[mf], bh[nf]);
                    mma_bf16(acc[mf][nf], ah[mf], bl[nf]);
                    mma_bf16(acc[mf][nf], al[mf], bh[nf]);
                }
        }
        __syncthreads();
    }
    const int gq = lane >> 2, t2 = (lane & 3) * 2;
    #pragma unroll
    for (int mf = 0; mf < 2; mf++) {
        const int row = m0 + wm + mf * 16 + gq;
        #pragma unroll
        for (int nf = 0; nf < 8; nf++) {
            const int col = n0 + wn + nf * 8 + t2;
            float2 v0, v1;
            v0.x = silu_f(acc[mf][nf][0]);
            v0.y = silu_f(acc[mf][nf][1]);
            v1.x = silu_f(acc[mf][nf][2]);
            v1.y = silu_f(acc[mf][nf][3]);
            *(float2*)(C + (size_t)row * D + col) = v0;
            *(float2*)(C + (size_t)(row + 8) * D + col) = v1;
        }
    }
}

// ---------------- l2norm + bf16 split of K and Q -----------------------------
__global__ __launch_bounds__(256) void l2norm_kernel(
    float* __restrict__ Kp, const float* __restrict__ Qp,
    __nv_bfloat16* __restrict__ Kh, __nv_bfloat16* __restrict__ Kl,
    __nv_bfloat16* __restrict__ Qh, __nv_bfloat16* __restrict__ Ql)
{
    const bool isK = (blockIdx.y == 0);
    const float* P = isK ? Kp : Qp;
    size_t base = (size_t)blockIdx.x * D + threadIdx.x * 4;
    float4 v = *(const float4*)(P + base);
    float ss = v.x * v.x + v.y * v.y + v.z * v.z + v.w * v.w;
    #pragma unroll
    for (int o = 16; o > 0; o >>= 1) ss += __shfl_xor_sync(0xffffffffu, ss, o);
    __shared__ float ws[8];
    if ((threadIdx.x & 31) == 0) ws[threadIdx.x >> 5] = ss;
    __syncthreads();
    float tot = 0.f;
    #pragma unroll
    for (int i = 0; i < 8; i++) tot += ws[i];
    float sc = 1.0f / (sqrtf(tot) + 1e-8f);
    v.x *= sc; v.y *= sc; v.z *= sc; v.w *= sc;
    if (isK) *(float4*)(Kp + base) = v;
    __nv_bfloat16* H = isK ? Kh : Qh;
    __nv_bfloat16* L = isK ? Kl : Ql;
    __nv_bfloat16 h0 = __float2bfloat16(v.x);
    __nv_bfloat16 h1 = __float2bfloat16(v.y);
    __nv_bfloat16 h2 = __float2bfloat16(v.z);
    __nv_bfloat16 h3 = __float2bfloat16(v.w);
    ushort4 HH, LL;
    HH.x = __bfloat16_as_ushort(h0); HH.y = __bfloat16_as_ushort(h1);
    HH.z = __bfloat16_as_ushort(h2); HH.w = __bfloat16_as_ushort(h3);
    LL.x = __bfloat16_as_ushort(__float2bfloat16(v.x - __bfloat162float(h0)));
    LL.y = __bfloat16_as_ushort(__float2bfloat16(v.y - __bfloat162float(h1)));
    LL.z = __bfloat16_as_ushort(__float2bfloat16(v.z - __bfloat162float(h2)));
    LL.w = __bfloat16_as_ushort(__float2bfloat16(v.w - __bfloat162float(h3)));
    *(ushort4*)(H + base) = HH;
    *(ushort4*)(L + base) = LL;
}

// ---------------- per-chunk forgetting gate: alpha[c] ------------------------
__global__ __launch_bounds__(256) void alpha_kernel(
    const float* __restrict__ Kp, const float* __restrict__ Wf, float* __restrict__ alpha)
{
    const int c = blockIdx.x, t = threadIdx.x;
    float4 wf = *(const float4*)(Wf + t * 4);
    const float* Kc = Kp + (size_t)c * CSZ * D;
    float s = 0.f;
    #pragma unroll 4
    for (int r = 0; r < CSZ; r++) {
        float4 kv = *(const float4*)(Kc + (size_t)r * D + t * 4);
        s += kv.x * wf.x + kv.y * wf.y + kv.z * wf.z + kv.w * wf.w;
    }
    #pragma unroll
    for (int o = 16; o > 0; o >>= 1) s += __shfl_xor_sync(0xffffffffu, s, o);
    __shared__ float ws[8];
    if ((t & 31) == 0) ws[t >> 5] = s;
    __syncthreads();
    if (t == 0) {
        float tot = 0.f;
        #pragma unroll
        for (int i = 0; i < 8; i++) tot += ws[i];
        float mean = tot * (1.0f / CSZ);
        alpha[c] = 0.1f / (1.0f + __expf(-mean));
    }
}

// ---------------- persistent sequential kernel (HMMA phases) ----------------
#define USTR_K 72
#define USTR_E 136
#define OA_STR 136
#define OB_STR 72
__global__ __launch_bounds__(256, 1) void titan_seq(
    const __nv_bfloat16* __restrict__ Kh, const __nv_bfloat16* __restrict__ Kl,
    const __nv_bfloat16* __restrict__ Qh, const __nv_bfloat16* __restrict__ Ql,
    const __nv_bfloat16* __restrict__ e0h, const __nv_bfloat16* __restrict__ e0l,
    __nv_bfloat16* __restrict__ errh, __nv_bfloat16* __restrict__ errl,
    const float* __restrict__ Vp, const float* __restrict__ alpha,
    float* __restrict__ M, float* __restrict__ S,
    __nv_bfloat16* __restrict__ Mh, __nv_bfloat16* __restrict__ Ml,
    float* __restrict__ out)
{
    extern __shared__ __nv_bfloat16 sm[];
    const int t = threadIdx.x, w = t >> 5, lane = t & 31;
    const int b = blockIdx.x;
    const int lt = lane >> 3, lr8 = lane & 7;
    const int gq = lane >> 2, t2 = (lane & 3) * 2;

    // zero-init M, S
    {
        float4 z = make_float4(0.f, 0.f, 0.f, 0.f);
        for (int idx = b * 256 + t; idx < D * D / 4; idx += NB * 256) {
            ((float4*)M)[idx] = z;
            ((float4*)S)[idx] = z;
        }
    }
    grid_sync();

    for (int c = 0; c < NCH; c++) {
        // ================= update phase: grad = Kc^T @ err; S,M; Mh/Ml ======
        {
            __nv_bfloat16* sKh = sm;
            __nv_bfloat16* sKl = sm + 128 * USTR_K;
            __nv_bfloat16* sEh = sm + 2 * 128 * USTR_K;
            __nv_bfloat16* sEl = sm + 2 * 128 * USTR_K + 128 * USTR_E;
            const int j0 = (b & 7) * 128, i0 = (b >> 3) * 64;
            const __nv_bfloat16* Kch = Kh + (size_t)c * CSZ * D;
            const __nv_bfloat16* Kcl = Kl + (size_t)c * CSZ * D;
            const __nv_bfloat16* Eh = (c == 0) ? e0h : errh;
            const __nv_bfloat16* El = (c == 0) ? e0l : errl;

            #pragma unroll
            for (int i = 0; i < 4; i++) {
                int idx = t + i * 256; int row = idx >> 3, q = idx & 7;
                *(uint4*)(sKh + row * USTR_K + q * 8) = *(const uint4*)(Kch + (size_t)row * D + i0 + q * 8);
                *(uint4*)(sKl + row * USTR_K + q * 8) = *(const uint4*)(Kcl + (size_t)row * D + i0 + q * 8);
            }
            #pragma unroll
            for (int i = 0; i < 8; i++) {
                int idx = t + i * 256; int row = idx >> 4, q = idx & 15;
                *(uint4*)(sEh + row * USTR_E + q * 8) = *(const uint4*)(Eh + (size_t)row * D + j0 + q * 8);
                *(uint4*)(sEl + row * USTR_E + q * 8) = *(const uint4*)(El + (size_t)row * D + j0 + q * 8);
            }
            __syncthreads();

            const int wi0 = (w & 3) * 16, wj0 = (w >> 2) * 64;
            const int a_r = (lt >> 1) * 8 + lr8, a_i = (lt & 1) * 8;
            const int b_k = (lt & 1) * 8 + lr8, b_n = (lt >> 1) * 8;
            const uint32_t uKh = smem_u32(sKh), uKl = smem_u32(sKl);
            const uint32_t uEh = smem_u32(sEh), uEl = smem_u32(sEl);

            float acc[8][4] = {};
            #pragma unroll
            for (int rs = 0; rs < 8; rs++) {
                uint32_t ah[4], al[4], bh[8][2], bl[8][2];
                uint32_t aoff = (uint32_t)(((rs * 16 + a_r) * USTR_K + wi0 + a_i) * 2);
                ldm_x4_t(ah, uKh + aoff);
                ldm_x4_t(al, uKl + aoff);
                #pragma unroll
                for (int jg = 0; jg < 4; jg++) {
                    uint32_t boff = (uint32_t)(((rs * 16 + b_k) * USTR_E + wj0 + jg * 16 + b_n) * 2);
                    uint32_t r[4];
                    ldm_x4_t(r, uEh + boff);
                    bh[2 * jg][0] = r[0]; bh[2 * jg][1] = r[1];
                    bh[2 * jg + 1][0] = r[2]; bh[2 * jg + 1][1] = r[3];
                    ldm_x4_t(r, uEl + boff);
                    bl[2 * jg][0] = r[0]; bl[2 * jg][1] = r[1];
                    bl[2 * jg + 1][0] = r[2]; bl[2 * jg + 1][1] = r[3];
                }
                #pragma unroll
                for (int nf = 0; nf < 8; nf++) {
                    mma_bf16(acc[nf], ah, bh[nf]);
                    mma_bf16(acc[nf], ah, bl[nf]);
                    mma_bf16(acc[nf], al, bh[nf]);
                }
            }
            const float alp = alpha[c];
            const float oma = 1.0f - alp;
            const float gs = ((c == 0) ? -1.0f : 1.0f) * (0.01f / CSZ);
            #pragma unroll
            for (int nf = 0; nf < 8; nf++) {
                #pragma unroll
                for (int h = 0; h < 2; h++) {
                    int row = i0 + wi0 + gq + h * 8;
                    int col = j0 + wj0 + nf * 8 + t2;
                    size_t idx = (size_t)row * D + col;
                    float2 s = *(float2*)(S + idx);
                    float2 m = *(float2*)(M + idx);
                    s.x = 0.9f * s.x - gs * acc[nf][h * 2 + 0];
                    s.y = 0.9f * s.y - gs * acc[nf][h * 2 + 1];
                    m.x = oma * m.x + s.x;
                    m.y = oma * m.y + s.y;
                    *(float2*)(S + idx) = s;
                    *(float2*)(M + idx) = m;
                    __nv_bfloat162 mh, ml;
                    mh.x = __float2bfloat16(m.x); mh.y = __float2bfloat16(m.y);
                    ml.x = __float2bfloat16(m.x - __bfloat162float(mh.x));
                    ml.y = __float2bfloat16(m.y - __bfloat162float(mh.y));
                    *(__nv_bfloat162*)(Mh + idx) = mh;
                    *(__nv_bfloat162*)(Ml + idx) = ml;
                }
            }
        }
        grid_sync();

        // ================= outerr phase: out = Q@M; err' = K@M - V ==========
        // 128 blocks: mt = b>>4 (8 m-tiles of 32 rows), n0 = (b&15)*64.
        // All 8 warps compute: warp tile 16m x 16n.
        {
            const int mt = b >> 4;
            const bool isQ = (mt < 4);
            if (c < NCH - 1 || isQ) {
                __nv_bfloat16* sAh = sm;
                __nv_bfloat16* sAl = sm + 32 * OA_STR;
                __nv_bfloat16* sBh = sm + 64 * OA_STR;
                __nv_bfloat16* sBl = sm + 64 * OA_STR + 128 * OB_STR;
                const int n0 = (b & 15) * 64;
                const __nv_bfloat16* Agh = isQ ? (Qh + ((size_t)c * CSZ + mt * 32) * D)
                                               : (Kh + ((size_t)(c + 1) * CSZ + (mt - 4) * 32) * D);
                const __nv_bfloat16* Agl = isQ ? (Ql + ((size_t)c * CSZ + mt * 32) * D)
                                               : (Kl + ((size_t)(c + 1) * CSZ + (mt - 4) * 32) * D);
                const int wm = (w & 1) * 16, wn = (w >> 1) * 16;
                const int a_m = (lt & 1) * 8 + lr8, a_k = (lt >> 1) * 8;
                const int b_k = (lt & 1) * 8 + lr8, b_n = (lt >> 1) * 8;
                const uint32_t uAh = smem_u32(sAh), uAl = smem_u32(sAl);
                const uint32_t uBh = smem_u32(sBh), uBl = smem_u32(sBl);

                float acc[2][4] = {};
                for (int kc = 0; kc < 8; kc++) {
                    __syncthreads();
                    #pragma unroll
                    for (int i = 0; i < 2; i++) {            // A: 32 x 128
                        int idx = t + i * 256; int row = idx >> 4, q = idx & 15;
                        *(uint4*)(sAh + row * OA_STR + q * 8) =
                            *(const uint4*)(Agh + (size_t)row * D + kc * 128 + q * 8);
                        *(uint4*)(sAl + row * OA_STR + q * 8) =
                            *(const uint4*)(Agl + (size_t)row * D + kc * 128 + q * 8);
                    }
                    #pragma unroll
                    for (int i = 0; i < 4; i++) {            // B: 128 x 64
                        int idx = t + i * 256; int row = idx >> 3, q = idx & 7;
                        *(uint4*)(sBh + row * OB_STR + q * 8) =
                            *(const uint4*)(Mh + (size_t)(kc * 128 + row) * D + n0 + q * 8);
                        *(uint4*)(sBl + row * OB_STR + q * 8) =
                            *(const uint4*)(Ml + (size_t)(kc * 128 + row) * D + n0 + q * 8);
                    }
                    __syncthreads();
                    #pragma unroll
                    for (int ks = 0; ks < 8; ks++) {
                        uint32_t ah[4], al[4], bh[2][2], bl[2][2];
                        uint32_t aoff = (uint32_t)(((wm + a_m) * OA_STR + ks * 16 + a_k) * 2);
                        ldm_x4(ah, uAh + aoff);
                        ldm_x4(al, uAl + aoff);
                        uint32_t boff = (uint32_t)(((ks * 16 + b_k) * OB_STR + wn + b_n) * 2);
                        uint32_t r[4];
                        ldm_x4_t(r, uBh + boff);
                        bh[0][0] = r[0]; bh[0][1] = r[1];
                        bh[1][0] = r[2]; bh[1][1] = r[3];
                        ldm_x4_t(r, uBl + boff);
                        bl[0][0] = r[0]; bl[0][1] = r[1];
                        bl[1][0] = r[2]; bl[1][1] = r[3];
                        #pragma unroll
                        for (int nf = 0; nf < 2; nf++) {
                            mma_bf16(acc[nf], ah, bh[nf]);
                            mma_bf16(acc[nf], ah, bl[nf]);
                            mma_bf16(acc[nf], al, bh[nf]);
                        }
                    }
                }
                if (isQ) {
                    #pragma unroll
                    for (int nf = 0; nf < 2; nf++)
                        #pragma unroll
                        for (int h = 0; h < 2; h++) {
                            int row = c * CSZ + mt * 32 + wm + gq + h * 8;
                            int col = n0 + wn + nf * 8 + t2;
                            *(float2*)(out + (size_t)row * D + col) =
                                make_float2(acc[nf][h * 2], acc[nf][h * 2 + 1]);
                        }
                } else {
                    #pragma unroll
                    for (int nf = 0; nf < 2; nf++)
                        #pragma unroll
                        for (int h = 0; h < 2; h++) {
                            int rl = (mt - 4) * 32 + wm + gq + h * 8;
                            int col = n0 + wn + nf * 8 + t2;
                            float2 vv = *(const float2*)(Vp + ((size_t)(c + 1) * CSZ + rl) * D + col);
                            float ex = acc[nf][h * 2] - vv.x;
                            float ey = acc[nf][h * 2 + 1] - vv.y;
                            __nv_bfloat162 hh, ll;
                            hh.x = __float2bfloat16(ex);
                            hh.y = __float2bfloat16(ey);
                            ll.x = __float2bfloat16(ex - __bfloat162float(hh.x));
                            ll.y = __float2bfloat16(ey - __bfloat162float(hh.y));
                            *(__nv_bfloat162*)(errh + (size_t)rl * D + col) = hh;
                            *(__nv_bfloat162*)(errl + (size_t)rl * D + col) = ll;
                        }
                }
            }
        }
        grid_sync();
    }
}

// ---------------- launcher ----------------------------------------------------
extern "C" void kernel_launch(void* const* d_in, const int* in_sizes, int n_in,
                              void* d_out, int out_size)
{
    const float* x  = (const float*)d_in[0];
    const float* Wk = (const float*)d_in[1];
    const float* Wv = (const float*)d_in[2];
    const float* Wq = (const float*)d_in[3];
    const float* Wf = (const float*)d_in[4];
    float* out = (float*)d_out;

    float *Kp, *Vp, *Qp, *Mp, *Sp, *alphap;
    __nv_bfloat16 *xh, *xl, *Wh, *Wl, *Khp, *Klp, *Qhp, *Qlp, *Mhp, *Mlp;
    __nv_bfloat16 *errhp, *errlp, *e0hp, *e0lp;
    cudaGetSymbolAddress((void**)&Kp, g_K);
    cudaGetSymbolAddress((void**)&Vp, g_V);
    cudaGetSymbolAddress((void**)&Qp, g_Q);
    cudaGetSymbolAddress((void**)&Mp, g_M);
    cudaGetSymbolAddress((void**)&Sp, g_S);
    cudaGetSymbolAddress((void**)&alphap, g_alpha);
    cudaGetSymbolAddress((void**)&xh, g_xh);
    cudaGetSymbolAddress((void**)&xl, g_xl);
    cudaGetSymbolAddress((void**)&Wh, g_Wh);
    cudaGetSymbolAddress((void**)&Wl, g_Wl);
    cudaGetSymbolAddress((void**)&Khp, g_Kh);
    cudaGetSymbolAddress((void**)&Klp, g_Kl);
    cudaGetSymbolAddress((void**)&Qhp, g_Qh);
    cudaGetSymbolAddress((void**)&Qlp, g_Ql);
    cudaGetSymbolAddress((void**)&Mhp, g_Mh);
    cudaGetSymbolAddress((void**)&Mlp, g_Ml);
    cudaGetSymbolAddress((void**)&errhp, g_errh);
    cudaGetSymbolAddress((void**)&errlp, g_errl);
    cudaGetSymbolAddress((void**)&e0hp, g_e0h);
    cudaGetSymbolAddress((void**)&e0lp, g_e0l);

    const int proj_smem = 4 * 128 * ASTR * 2;                        // 73728
    const int seq_smem  = (2 * 128 * USTR_K + 2 * 128 * USTR_E) * 2; // 106496
    cudaFuncSetAttribute(projmma_kernel, cudaFuncAttributeMaxDynamicSharedMemorySize, proj_smem);
    cudaFuncSetAttribute(titan_seq, cudaFuncAttributeMaxDynamicSharedMemorySize, seq_smem);

    // Parallel phase.
    convert_kernel<<<SEQ_LEN * D / 1024, 256>>>(x, xh, xl);
    convert_kernel<<<D * D / 1024, 256>>>(Wk, Wh, Wl);
    convert_kernel<<<D * D / 1024, 256>>>(Wv, Wh + D * D, Wl + D * D);
    convert_kernel<<<D * D / 1024, 256>>>(Wq, Wh + 2 * D * D, Wl + 2 * D * D);
    projmma_kernel<<<dim3(SEQ_LEN / 128, D / 128, 3), 256, proj_smem>>>(
        xh, xl, Wh, Wl, Kp, Vp, Qp);
    l2norm_kernel<<<dim3(SEQ_LEN, 2), 256>>>(Kp, Qp, Khp, Klp, Qhp, Qlp);
    alpha_kernel<<<NCH, 256>>>(Kp, Wf, alphap);
    convert_kernel<<<CSZ * D / 1024, 256>>>(Vp, e0hp, e0lp);   // err_0 = -V_0 via gs sign

    // Sequential phase: ONE persistent kernel, HMMA phases, fast grid barrier.
    titan_seq<<<NB, 256, seq_smem>>>(Khp, Klp, Qhp, Qlp, e0hp, e0lp,
                                     errhp, errlp, Vp, alphap,
                                     Mp, Sp, Mhp, Mlp, out);
}